// round 4
// baseline (speedup 1.0000x reference)
#include <cuda_runtime.h>
#include <math.h>

#define L_LAYERS 3
#define D_DIM    128
#define A_DIM    64
#define NREL     401
#define N_NODE   100000
#define N_EDGE   600000
#define NQ_C     512
#define N_DELTA  731
#define MAX_OUT  (512*50000)

typedef unsigned long long u64;

// ---------------- static device scratch (no allocations allowed) ----------------
__device__ float g_hprev  [N_NODE * D_DIM];
__device__ float g_hidden1[N_NODE * D_DIM];
__device__ float g_agg    [N_NODE * D_DIM];
__device__ float g_gi     [N_NODE * 3 * D_DIM];
__device__ float g_gh     [N_NODE * 3 * D_DIM];
__device__ float g_HS     [N_NODE * A_DIM];
__device__ float g_Rattn  [NREL * A_DIM];
__device__ float g_Qattn  [NQ_C * A_DIM];
__device__ float g_Hattn  [N_DELTA * A_DIM];
__device__ float g_Hmsg   [N_DELTA * D_DIM];
__device__ int   g_winner [MAX_OUT];

__device__ __forceinline__ float sigmoidf_(float x) { return 1.0f / (1.0f + expf(-x)); }

// packed fp32x2 FMA (Blackwell): d = a*b + c elementwise on 32-bit halves.
__device__ __forceinline__ u64 ffma2(u64 a, u64 b, u64 c) {
    u64 d;
    asm("fma.rn.f32x2 %0, %1, %2, %3;" : "=l"(d) : "l"(a), "l"(b), "l"(c));
    return d;
}
__device__ __forceinline__ u64 d2u(double x) { return __double_as_longlong(x); }

// ---------------- per-relation / per-query attention tables ----------------
__global__ void k_tab_rq(const float* __restrict__ rela_l,
                         const float* __restrict__ Wr_l,
                         const float* __restrict__ Wqr_w_l,
                         const float* __restrict__ Wqr_b_l,
                         const int*   __restrict__ q_rel,
                         float* __restrict__ Rattn,
                         float* __restrict__ Qattn)
{
    __shared__ float hv[128];
    int b = blockIdx.x;
    int a = threadIdx.x; // 0..63
    const float* src = (b < NREL) ? (rela_l + (size_t)b * 128)
                                  : (rela_l + (size_t)q_rel[b - NREL] * 128);
    hv[a] = src[a];
    hv[a + 64] = src[a + 64];
    __syncthreads();
    const float* W = ((b < NREL) ? Wr_l : Wqr_w_l) + (size_t)a * 128;
    float s = 0.f;
#pragma unroll
    for (int k = 0; k < 128; k += 4) {
        float4 w = *(const float4*)(W + k);
        s += hv[k] * w.x + hv[k + 1] * w.y + hv[k + 2] * w.z + hv[k + 3] * w.w;
    }
    if (b < NREL) Rattn[b * 64 + a] = s;
    else          Qattn[(b - NREL) * 64 + a] = s + Wqr_b_l[a];
}

// ---------------- per-delta tables: h_hau vector + h_hau @ Wtau^T ----------------
__global__ void k_tab_delta(const float* __restrict__ wt1, const float* __restrict__ bt1,
                            const float* __restrict__ wt2, const float* __restrict__ bt2,
                            const float* __restrict__ Wtau_l,
                            float* __restrict__ Hmsg, float* __restrict__ Hattn)
{
    __shared__ float hh[128];
    int di = blockIdx.x;           // 0..730
    float delta = (float)(di - 365);
    int d = threadIdx.x;           // 0..127
    float v = wt1[d] * delta + bt1[d] + sinf(wt2[d] * delta + bt2[d]);
    hh[d] = v;
    Hmsg[(size_t)di * 128 + d] = v;
    __syncthreads();
    if (d < 64) {
        const float* W = Wtau_l + (size_t)d * 128;
        float s = 0.f;
#pragma unroll
        for (int k = 0; k < 128; k += 4) {
            float4 w = *(const float4*)(W + k);
            s += hh[k] * w.x + hh[k + 1] * w.y + hh[k + 2] * w.z + hh[k + 3] * w.w;
        }
        Hattn[(size_t)di * 64 + d] = s;
    }
}

// ---------------- edge kernel: one warp per edge ----------------
__global__ void __launch_bounds__(256) k_edge(
    const int* __restrict__ e_sub, const int* __restrict__ e_rel,
    const int* __restrict__ e_obj, const int* __restrict__ e_ridx,
    const int* __restrict__ e_tau, const int* __restrict__ q_tau,
    const float* __restrict__ HS, const float* __restrict__ Rattn,
    const float* __restrict__ Qattn, const float* __restrict__ Hattn,
    const float* __restrict__ Hmsg, const float* __restrict__ hprev,
    const float* __restrict__ rela_l, const float* __restrict__ walpha_w_l,
    const float* __restrict__ walpha_b_l, float* __restrict__ agg)
{
    int e = (int)((blockIdx.x * blockDim.x + threadIdx.x) >> 5);
    int lane = threadIdx.x & 31;
    if (e >= N_EDGE) return;

    int s_ = e_sub[e];
    int r_ = e_rel[e];
    int o_ = e_obj[e];
    int q_ = e_ridx[e];
    int t_ = e_tau[e];
    int tq = q_tau[q_];
    int tau = (t_ >= 0) ? t_ : tq;
    int di = tau - tq + 365;
    di = min(max(di, 0), 730);

    float2 hs2 = ((const float2*)HS)   [(size_t)s_ * 32 + lane];
    float2 rr2 = ((const float2*)Rattn)[(size_t)r_ * 32 + lane];
    float2 qq2 = ((const float2*)Qattn)[(size_t)q_ * 32 + lane];
    float2 tt2 = ((const float2*)Hattn)[(size_t)di * 32 + lane];
    float vx = fmaxf(hs2.x + rr2.x + qq2.x + tt2.x, 0.f);
    float vy = fmaxf(hs2.y + rr2.y + qq2.y + tt2.y, 0.f);
    float2 wa = ((const float2*)walpha_w_l)[lane];
    float acc = vx * wa.x + vy * wa.y;
#pragma unroll
    for (int off = 16; off; off >>= 1) acc += __shfl_xor_sync(0xffffffffu, acc, off);
    float alpha = 1.0f / (1.0f + expf(-(acc + walpha_b_l[0])));

    float4 h4 = ((const float4*)hprev) [(size_t)s_ * 32 + lane];
    float4 r4 = ((const float4*)rela_l)[(size_t)r_ * 32 + lane];
    float4 m4 = ((const float4*)Hmsg)  [(size_t)di * 32 + lane];
    float mx = alpha * (h4.x + r4.x + m4.x);
    float my = alpha * (h4.y + r4.y + m4.y);
    float mz = alpha * (h4.z + r4.z + m4.z);
    float mw = alpha * (h4.w + r4.w + m4.w);
    float* dst = agg + (size_t)o_ * 128 + lane * 4;
    asm volatile("red.global.add.v4.f32 [%0], {%1,%2,%3,%4};"
                 :: "l"(dst), "f"(mx), "f"(my), "f"(mz), "f"(mw) : "memory");
}

// ---------------- SGEMM with packed f32x2 FMA ----------------
// C[M,NOUT] = A[M,128] @ W[NOUT,128]^T (+bias)(+relu)
// BM=BN=128, BK=8, 256 threads, 8x8 per-thread tile.
// Accumulator pairs span adjacent ROWS (natural pairs from As),
// B duplicated in smem so dup-pairs come straight from LDS.128 -> no pack MOVs.
__global__ void __launch_bounds__(256, 2) k_sgemm(
    const float* __restrict__ A, const float* __restrict__ W,
    const float* __restrict__ bias, float* __restrict__ C,
    int M, int NOUT, int relu)
{
    __shared__ float As[8][128];
    __shared__ float Bs[8][256];  // duplicated: Bs[k][2c] == Bs[k][2c+1]
    int bm = blockIdx.x * 128;
    int bn = blockIdx.y * 128;
    int tid = threadIdx.x;
    int lr = tid >> 1;            // 0..127 row-in-tile for loads
    int lc = (tid & 1) * 4;       // 0 or 4  k-offset for loads
    int tm = (tid >> 4) * 8;      // 0..120
    int tn = (tid & 15) * 8;      // 0..120
    bool aval = (bm + lr) < M;
    bool bval = (bn + lr) < NOUT;
    const float* Ap = A + (size_t)(bm + lr) * 128 + lc;
    const float* Bp = W + (size_t)(bn + lr) * 128 + lc;

    u64 acc[4][8];
#pragma unroll
    for (int i = 0; i < 4; i++)
#pragma unroll
        for (int j = 0; j < 8; j++) acc[i][j] = 0ull;

    for (int kt = 0; kt < 128; kt += 8) {
        float4 a4 = aval ? *(const float4*)(Ap + kt) : make_float4(0.f, 0.f, 0.f, 0.f);
        float4 b4 = bval ? *(const float4*)(Bp + kt) : make_float4(0.f, 0.f, 0.f, 0.f);
        As[lc + 0][lr] = a4.x; As[lc + 1][lr] = a4.y;
        As[lc + 2][lr] = a4.z; As[lc + 3][lr] = a4.w;
        *(float2*)&Bs[lc + 0][2 * lr] = make_float2(b4.x, b4.x);
        *(float2*)&Bs[lc + 1][2 * lr] = make_float2(b4.y, b4.y);
        *(float2*)&Bs[lc + 2][2 * lr] = make_float2(b4.z, b4.z);
        *(float2*)&Bs[lc + 3][2 * lr] = make_float2(b4.w, b4.w);
        __syncthreads();
#pragma unroll
        for (int kk = 0; kk < 8; kk++) {
            double2 a01 = *(const double2*)&As[kk][tm];       // rows tm..tm+3 (2 pairs)
            double2 a23 = *(const double2*)&As[kk][tm + 4];   // rows tm+4..tm+7
            double2 bb0 = *(const double2*)&Bs[kk][2 * tn];       // cols j0,j1 dup
            double2 bb1 = *(const double2*)&Bs[kk][2 * tn + 4];   // j2,j3
            double2 bb2 = *(const double2*)&Bs[kk][2 * tn + 8];   // j4,j5
            double2 bb3 = *(const double2*)&Bs[kk][2 * tn + 12];  // j6,j7
            u64 ap[4] = { d2u(a01.x), d2u(a01.y), d2u(a23.x), d2u(a23.y) };
            u64 bp[8] = { d2u(bb0.x), d2u(bb0.y), d2u(bb1.x), d2u(bb1.y),
                          d2u(bb2.x), d2u(bb2.y), d2u(bb3.x), d2u(bb3.y) };
#pragma unroll
            for (int i = 0; i < 4; i++)
#pragma unroll
                for (int j = 0; j < 8; j++)
                    acc[i][j] = ffma2(ap[i], bp[j], acc[i][j]);
        }
        __syncthreads();
    }

    // epilogue: acc[i4][j] low half = row tm+2*i4, high half = row tm+2*i4+1, col tn+j
#pragma unroll
    for (int i4 = 0; i4 < 4; i4++) {
#pragma unroll
        for (int h = 0; h < 2; h++) {
            int row = bm + tm + 2 * i4 + h;
            if (row >= M) continue;
#pragma unroll
            for (int j0 = 0; j0 < 8; j0 += 4) {
                int col = bn + tn + j0;
                if (col >= NOUT) continue;
                float4 v;
                if (h == 0) {
                    v.x = __uint_as_float((unsigned)(acc[i4][j0 + 0] & 0xffffffffull));
                    v.y = __uint_as_float((unsigned)(acc[i4][j0 + 1] & 0xffffffffull));
                    v.z = __uint_as_float((unsigned)(acc[i4][j0 + 2] & 0xffffffffull));
                    v.w = __uint_as_float((unsigned)(acc[i4][j0 + 3] & 0xffffffffull));
                } else {
                    v.x = __uint_as_float((unsigned)(acc[i4][j0 + 0] >> 32));
                    v.y = __uint_as_float((unsigned)(acc[i4][j0 + 1] >> 32));
                    v.z = __uint_as_float((unsigned)(acc[i4][j0 + 2] >> 32));
                    v.w = __uint_as_float((unsigned)(acc[i4][j0 + 3] >> 32));
                }
                if (bias) {
                    v.x += bias[col]; v.y += bias[col + 1];
                    v.z += bias[col + 2]; v.w += bias[col + 3];
                }
                if (relu) {
                    v.x = fmaxf(v.x, 0.f); v.y = fmaxf(v.y, 0.f);
                    v.z = fmaxf(v.z, 0.f); v.w = fmaxf(v.w, 0.f);
                }
                *(float4*)(C + (size_t)row * NOUT + col) = v;
            }
        }
    }
}

// ---------------- GRU elementwise (PyTorch semantics), in-place on h ----------------
__global__ void k_gru(const float* __restrict__ gi, const float* __restrict__ gh,
                      float* __restrict__ h)
{
    int idx = blockIdx.x * blockDim.x + threadIdx.x;  // node*32 + g
    if (idx >= N_NODE * 32) return;
    int n = idx >> 5, g = idx & 31;
    const float4* gi4 = (const float4*)(gi + (size_t)n * 384);
    const float4* gh4 = (const float4*)(gh + (size_t)n * 384);
    float4 ir = gi4[g],      iz = gi4[32 + g], in_ = gi4[64 + g];
    float4 hr = gh4[g],      hz = gh4[32 + g], hn  = gh4[64 + g];
    float4 h0 = ((const float4*)h)[(size_t)n * 32 + g];
    float4 out;
    {
        float r = sigmoidf_(ir.x + hr.x), z = sigmoidf_(iz.x + hz.x);
        float nn = tanhf(in_.x + r * hn.x);
        out.x = (1.f - z) * nn + z * h0.x;
    }
    {
        float r = sigmoidf_(ir.y + hr.y), z = sigmoidf_(iz.y + hz.y);
        float nn = tanhf(in_.y + r * hn.y);
        out.y = (1.f - z) * nn + z * h0.y;
    }
    {
        float r = sigmoidf_(ir.z + hr.z), z = sigmoidf_(iz.z + hz.z);
        float nn = tanhf(in_.z + r * hn.z);
        out.z = (1.f - z) * nn + z * h0.z;
    }
    {
        float r = sigmoidf_(ir.w + hr.w), z = sigmoidf_(iz.w + hz.w);
        float nn = tanhf(in_.w + r * hn.w);
        out.w = (1.f - z) * nn + z * h0.w;
    }
    ((float4*)h)[(size_t)n * 32 + g] = out;
}

// ---------------- output scatter: deterministic last-index-wins on collisions ----------------
__global__ void k_scat1(const int* __restrict__ nb, const int* __restrict__ ne,
                        int* __restrict__ winner, int n_ent)
{
    int n = blockIdx.x * blockDim.x + threadIdx.x;
    if (n >= N_NODE) return;
    size_t slot = (size_t)nb[n] * n_ent + ne[n];
    atomicMax(&winner[slot], n);
}

__global__ void k_scat2(const float* __restrict__ h, const float* __restrict__ Wfinal,
                        const int* __restrict__ nb, const int* __restrict__ ne,
                        const int* __restrict__ winner, float* __restrict__ out, int n_ent)
{
    int n = (int)((blockIdx.x * blockDim.x + threadIdx.x) >> 5);
    int lane = threadIdx.x & 31;
    if (n >= N_NODE) return;
    float4 hv = ((const float4*)h)[(size_t)n * 32 + lane];
    float4 wv = ((const float4*)Wfinal)[lane];
    float s = hv.x * wv.x + hv.y * wv.y + hv.z * wv.z + hv.w * wv.w;
#pragma unroll
    for (int off = 16; off; off >>= 1) s += __shfl_xor_sync(0xffffffffu, s, off);
    if (lane == 0) {
        size_t slot = (size_t)nb[n] * n_ent + ne[n];
        if (winner[slot] == n) out[slot] = s;
    }
}

// ---------------- host launcher ----------------
extern "C" void kernel_launch(void* const* d_in, const int* in_sizes, int n_in,
                              void* d_out, int out_size)
{
    const float* rela     = (const float*)d_in[0];
    const float* Ws       = (const float*)d_in[1];
    const float* Wr       = (const float*)d_in[2];
    const float* Wqr_w    = (const float*)d_in[3];
    const float* Wqr_b    = (const float*)d_in[4];
    const float* Wtau     = (const float*)d_in[5];
    const float* walpha_w = (const float*)d_in[6];
    const float* walpha_b = (const float*)d_in[7];
    const float* Wh       = (const float*)d_in[8];
    const float* wt1      = (const float*)d_in[9];
    const float* bt1      = (const float*)d_in[10];
    const float* wt2      = (const float*)d_in[11];
    const float* bt2      = (const float*)d_in[12];
    const float* Wih      = (const float*)d_in[13];
    const float* Whh      = (const float*)d_in[14];
    const float* bih      = (const float*)d_in[15];
    const float* bhh      = (const float*)d_in[16];
    const float* Wfinal   = (const float*)d_in[17];
    const int*   q_rel    = (const int*)d_in[18];
    const int*   q_tau    = (const int*)d_in[19];
    const int*   e_ridx   = (const int*)d_in[20];
    const int*   e_rel    = (const int*)d_in[21];
    const int*   e_tau    = (const int*)d_in[22];
    const int*   e_sub    = (const int*)d_in[23];
    const int*   e_obj    = (const int*)d_in[24];
    const int*   nb       = (const int*)d_in[25];
    const int*   ne       = (const int*)d_in[26];

    int nq    = in_sizes[18];
    int n_ent = out_size / nq;

    float *hprev, *hidden1, *agg, *gi, *gh, *HS, *Rattn, *Qattn, *Hattn, *Hmsg;
    int* winner;
    cudaGetSymbolAddress((void**)&hprev,   g_hprev);
    cudaGetSymbolAddress((void**)&hidden1, g_hidden1);
    cudaGetSymbolAddress((void**)&agg,     g_agg);
    cudaGetSymbolAddress((void**)&gi,      g_gi);
    cudaGetSymbolAddress((void**)&gh,      g_gh);
    cudaGetSymbolAddress((void**)&HS,      g_HS);
    cudaGetSymbolAddress((void**)&Rattn,   g_Rattn);
    cudaGetSymbolAddress((void**)&Qattn,   g_Qattn);
    cudaGetSymbolAddress((void**)&Hattn,   g_Hattn);
    cudaGetSymbolAddress((void**)&Hmsg,    g_Hmsg);
    cudaGetSymbolAddress((void**)&winner,  g_winner);

    cudaMemsetAsync(hprev, 0, sizeof(float) * (size_t)N_NODE * D_DIM);

    const int mblocks = (N_NODE + 127) / 128;   // 782
    dim3 gM1(mblocks, 1), gM3(mblocks, 3);

    for (int l = 0; l < L_LAYERS; l++) {
        cudaMemsetAsync(agg, 0, sizeof(float) * (size_t)N_NODE * D_DIM);

        k_tab_rq<<<NREL + NQ_C, 64>>>(rela + (size_t)l * NREL * 128,
                                      Wr + (size_t)l * 64 * 128,
                                      Wqr_w + (size_t)l * 64 * 128,
                                      Wqr_b + (size_t)l * 64,
                                      q_rel, Rattn, Qattn);
        k_tab_delta<<<N_DELTA, 128>>>(wt1 + (size_t)l * 128, bt1 + (size_t)l * 128,
                                      wt2 + (size_t)l * 128, bt2 + (size_t)l * 128,
                                      Wtau + (size_t)l * 64 * 128, Hmsg, Hattn);
        // HS = hprev @ Ws^T  [N_NODE, 64]
        k_sgemm<<<gM1, 256>>>(hprev, Ws + (size_t)l * 64 * 128, nullptr, HS, N_NODE, 64, 0);

        k_edge<<<N_EDGE / 8, 256>>>(e_sub + (size_t)l * N_EDGE, e_rel + (size_t)l * N_EDGE,
                                    e_obj + (size_t)l * N_EDGE, e_ridx + (size_t)l * N_EDGE,
                                    e_tau + (size_t)l * N_EDGE, q_tau,
                                    HS, Rattn, Qattn, Hattn, Hmsg, hprev,
                                    rela + (size_t)l * NREL * 128,
                                    walpha_w + (size_t)l * 64, walpha_b + l, agg);

        // hidden1 = relu(agg @ Wh^T)
        k_sgemm<<<gM1, 256>>>(agg, Wh + (size_t)l * 128 * 128, nullptr, hidden1, N_NODE, 128, 1);
        // gi = hidden1 @ Wih^T + bih
        k_sgemm<<<gM3, 256>>>(hidden1, Wih + (size_t)l * 384 * 128, bih + (size_t)l * 384,
                              gi, N_NODE, 384, 0);
        // gh = hprev @ Whh^T + bhh
        k_sgemm<<<gM3, 256>>>(hprev, Whh + (size_t)l * 384 * 128, bhh + (size_t)l * 384,
                              gh, N_NODE, 384, 0);
        // hprev <- GRU
        k_gru<<<(N_NODE * 32) / 256, 256>>>(gi, gh, hprev);
    }

    cudaMemsetAsync(d_out, 0, (size_t)out_size * sizeof(float));
    cudaMemsetAsync(winner, 0xFF, (size_t)out_size * sizeof(int));
    k_scat1<<<(N_NODE + 255) / 256, 256>>>(nb, ne, winner, n_ent);
    k_scat2<<<(N_NODE * 32) / 256, 256>>>(hprev, Wfinal, nb, ne, winner, (float*)d_out, n_ent);
}

// round 5
// speedup vs baseline: 2.1041x; 2.1041x over previous
#include <cuda_runtime.h>
#include <math.h>

#define L_LAYERS 3
#define D_DIM    128
#define A_DIM    64
#define NREL     401
#define N_NODE   100000
#define N_EDGE   600000
#define NQ_C     512
#define N_DELTA  731
#define MAX_OUT  (512*50000)

// smem for k_mma: As[128][132] float2 + Bs[64][132] float2
#define MMA_STRIDE 132
#define SMEM_MMA   ((128 + 64) * MMA_STRIDE * 8)

// ---------------- static device scratch (no allocations allowed) ----------------
__device__ float g_hprev  [N_NODE * D_DIM];
__device__ float g_hidden1[N_NODE * D_DIM];
__device__ float g_agg    [N_NODE * D_DIM];
__device__ float g_gi     [N_NODE * 3 * D_DIM];
__device__ float g_gh     [N_NODE * 3 * D_DIM];
__device__ float g_HS     [N_NODE * A_DIM];
__device__ float g_Rattn  [NREL * A_DIM];
__device__ float g_Qattn  [NQ_C * A_DIM];
__device__ float g_Hattn  [N_DELTA * A_DIM];
__device__ float g_Hmsg   [N_DELTA * D_DIM];
__device__ int   g_winner [MAX_OUT];

__device__ __forceinline__ float sigmoidf_(float x) { return 1.0f / (1.0f + expf(-x)); }

// split fp32 -> (tf32 hi, tf32 lo) stored as float bit patterns
__device__ __forceinline__ float2 tf32_split(float x) {
    unsigned hi;
    asm("cvt.rna.tf32.f32 %0, %1;" : "=r"(hi) : "f"(x));
    float hif = __uint_as_float(hi);
    float lo = x - hif;
    unsigned lob;
    asm("cvt.rna.tf32.f32 %0, %1;" : "=r"(lob) : "f"(lo));
    return make_float2(hif, __uint_as_float(lob));
}

__device__ __forceinline__ void mma_tf32(float* c,
                                         unsigned a0, unsigned a1, unsigned a2, unsigned a3,
                                         unsigned b0, unsigned b1) {
    asm volatile(
        "mma.sync.aligned.m16n8k8.row.col.f32.tf32.tf32.f32 "
        "{%0,%1,%2,%3}, {%4,%5,%6,%7}, {%8,%9}, {%0,%1,%2,%3};"
        : "+f"(c[0]), "+f"(c[1]), "+f"(c[2]), "+f"(c[3])
        : "r"(a0), "r"(a1), "r"(a2), "r"(a3), "r"(b0), "r"(b1));
}

// ---------------- per-relation / per-query attention tables ----------------
__global__ void k_tab_rq(const float* __restrict__ rela_l,
                         const float* __restrict__ Wr_l,
                         const float* __restrict__ Wqr_w_l,
                         const float* __restrict__ Wqr_b_l,
                         const int*   __restrict__ q_rel,
                         float* __restrict__ Rattn,
                         float* __restrict__ Qattn)
{
    __shared__ float hv[128];
    int b = blockIdx.x;
    int a = threadIdx.x; // 0..63
    const float* src = (b < NREL) ? (rela_l + (size_t)b * 128)
                                  : (rela_l + (size_t)q_rel[b - NREL] * 128);
    hv[a] = src[a];
    hv[a + 64] = src[a + 64];
    __syncthreads();
    const float* W = ((b < NREL) ? Wr_l : Wqr_w_l) + (size_t)a * 128;
    float s = 0.f;
#pragma unroll
    for (int k = 0; k < 128; k += 4) {
        float4 w = *(const float4*)(W + k);
        s += hv[k] * w.x + hv[k + 1] * w.y + hv[k + 2] * w.z + hv[k + 3] * w.w;
    }
    if (b < NREL) Rattn[b * 64 + a] = s;
    else          Qattn[(b - NREL) * 64 + a] = s + Wqr_b_l[a];
}

// ---------------- per-delta tables: h_hau vector + h_hau @ Wtau^T ----------------
__global__ void k_tab_delta(const float* __restrict__ wt1, const float* __restrict__ bt1,
                            const float* __restrict__ wt2, const float* __restrict__ bt2,
                            const float* __restrict__ Wtau_l,
                            float* __restrict__ Hmsg, float* __restrict__ Hattn)
{
    __shared__ float hh[128];
    int di = blockIdx.x;           // 0..730
    float delta = (float)(di - 365);
    int d = threadIdx.x;           // 0..127
    float v = wt1[d] * delta + bt1[d] + sinf(wt2[d] * delta + bt2[d]);
    hh[d] = v;
    Hmsg[(size_t)di * 128 + d] = v;
    __syncthreads();
    if (d < 64) {
        const float* W = Wtau_l + (size_t)d * 128;
        float s = 0.f;
#pragma unroll
        for (int k = 0; k < 128; k += 4) {
            float4 w = *(const float4*)(W + k);
            s += hh[k] * w.x + hh[k + 1] * w.y + hh[k + 2] * w.z + hh[k + 3] * w.w;
        }
        Hattn[(size_t)di * 64 + d] = s;
    }
}

// ---------------- edge kernel: one warp per edge ----------------
__global__ void __launch_bounds__(256) k_edge(
    const int* __restrict__ e_sub, const int* __restrict__ e_rel,
    const int* __restrict__ e_obj, const int* __restrict__ e_ridx,
    const int* __restrict__ e_tau, const int* __restrict__ q_tau,
    const float* __restrict__ HS, const float* __restrict__ Rattn,
    const float* __restrict__ Qattn, const float* __restrict__ Hattn,
    const float* __restrict__ Hmsg, const float* __restrict__ hprev,
    const float* __restrict__ rela_l, const float* __restrict__ walpha_w_l,
    const float* __restrict__ walpha_b_l, float* __restrict__ agg)
{
    int e = (int)((blockIdx.x * blockDim.x + threadIdx.x) >> 5);
    int lane = threadIdx.x & 31;
    if (e >= N_EDGE) return;

    int s_ = e_sub[e];
    int r_ = e_rel[e];
    int o_ = e_obj[e];
    int q_ = e_ridx[e];
    int t_ = e_tau[e];
    int tq = q_tau[q_];
    int tau = (t_ >= 0) ? t_ : tq;
    int di = tau - tq + 365;
    di = min(max(di, 0), 730);

    float2 hs2 = ((const float2*)HS)   [(size_t)s_ * 32 + lane];
    float2 rr2 = ((const float2*)Rattn)[(size_t)r_ * 32 + lane];
    float2 qq2 = ((const float2*)Qattn)[(size_t)q_ * 32 + lane];
    float2 tt2 = ((const float2*)Hattn)[(size_t)di * 32 + lane];
    float vx = fmaxf(hs2.x + rr2.x + qq2.x + tt2.x, 0.f);
    float vy = fmaxf(hs2.y + rr2.y + qq2.y + tt2.y, 0.f);
    float2 wa = ((const float2*)walpha_w_l)[lane];
    float acc = vx * wa.x + vy * wa.y;
#pragma unroll
    for (int off = 16; off; off >>= 1) acc += __shfl_xor_sync(0xffffffffu, acc, off);
    float alpha = 1.0f / (1.0f + expf(-(acc + walpha_b_l[0])));

    float4 h4 = ((const float4*)hprev) [(size_t)s_ * 32 + lane];
    float4 r4 = ((const float4*)rela_l)[(size_t)r_ * 32 + lane];
    float4 m4 = ((const float4*)Hmsg)  [(size_t)di * 32 + lane];
    float mx = alpha * (h4.x + r4.x + m4.x);
    float my = alpha * (h4.y + r4.y + m4.y);
    float mz = alpha * (h4.z + r4.z + m4.z);
    float mw = alpha * (h4.w + r4.w + m4.w);
    float* dst = agg + (size_t)o_ * 128 + lane * 4;
    asm volatile("red.global.add.v4.f32 [%0], {%1,%2,%3,%4};"
                 :: "l"(dst), "f"(mx), "f"(my), "f"(mz), "f"(mw) : "memory");
}

// ---------------- tensor-core GEMM (tf32 split, fp32-accurate) ----------------
// C[M,NOUT] = A[M,128] @ W[NOUT,128]^T (+bias)(+relu), NOUT multiple of 64.
// Block: 256 thr = 8 warps (4m x 2n), BM=128. A tile resident in smem (split),
// internal loop over 64-wide n-tiles reloading only B.
__global__ void __launch_bounds__(256) k_mma(
    const float* __restrict__ A, const float* __restrict__ W,
    const float* __restrict__ bias, float* __restrict__ C,
    int M, int NOUT, int relu)
{
    extern __shared__ float2 sm2[];
    float2* As = sm2;                       // [128][MMA_STRIDE]
    float2* Bs = sm2 + 128 * MMA_STRIDE;    // [64][MMA_STRIDE]

    int tid  = threadIdx.x;
    int bm   = blockIdx.x * 128;
    int lane = tid & 31;
    int warp = tid >> 5;
    int wm   = (warp & 3) * 32;   // 0,32,64,96
    int wn   = (warp >> 2) * 32;  // 0,32
    int gr   = lane >> 2;         // 0..7
    int tg   = lane & 3;          // 0..3

    // ---- load + split A tile (128 x 128) ----
    for (int i = tid; i < 128 * 32; i += 256) {
        int row = i >> 5;
        int c4  = (i & 31) * 4;
        int grow = bm + row;
        float4 v = (grow < M) ? *(const float4*)(A + (size_t)grow * 128 + c4)
                              : make_float4(0.f, 0.f, 0.f, 0.f);
        float2* dst = As + row * MMA_STRIDE + c4;
        dst[0] = tf32_split(v.x); dst[1] = tf32_split(v.y);
        dst[2] = tf32_split(v.z); dst[3] = tf32_split(v.w);
    }
    __syncthreads();

    for (int nb = 0; nb < NOUT; nb += 64) {
        // ---- load + split B tile (64 x 128) ----
        for (int i = tid; i < 64 * 32; i += 256) {
            int row = i >> 5;
            int c4  = (i & 31) * 4;
            float4 v = *(const float4*)(W + (size_t)(nb + row) * 128 + c4);
            float2* dst = Bs + row * MMA_STRIDE + c4;
            dst[0] = tf32_split(v.x); dst[1] = tf32_split(v.y);
            dst[2] = tf32_split(v.z); dst[3] = tf32_split(v.w);
        }
        __syncthreads();

        float acc[2][4][4];
#pragma unroll
        for (int mt = 0; mt < 2; mt++)
#pragma unroll
            for (int nt = 0; nt < 4; nt++)
#pragma unroll
                for (int r = 0; r < 4; r++) acc[mt][nt][r] = 0.f;

#pragma unroll
        for (int kk = 0; kk < 128; kk += 8) {
            float2 af[2][4];
#pragma unroll
            for (int mt = 0; mt < 2; mt++) {
                const float2* ap = As + (wm + mt * 16 + gr) * MMA_STRIDE + kk + tg;
                af[mt][0] = ap[0];
                af[mt][1] = ap[8 * MMA_STRIDE];
                af[mt][2] = ap[4];
                af[mt][3] = ap[8 * MMA_STRIDE + 4];
            }
            float2 bf[4][2];
#pragma unroll
            for (int nt = 0; nt < 4; nt++) {
                const float2* bp = Bs + (wn + nt * 8 + gr) * MMA_STRIDE + kk + tg;
                bf[nt][0] = bp[0];
                bf[nt][1] = bp[4];
            }
#pragma unroll
            for (int mt = 0; mt < 2; mt++) {
                unsigned ah0 = __float_as_uint(af[mt][0].x), ah1 = __float_as_uint(af[mt][1].x);
                unsigned ah2 = __float_as_uint(af[mt][2].x), ah3 = __float_as_uint(af[mt][3].x);
                unsigned al0 = __float_as_uint(af[mt][0].y), al1 = __float_as_uint(af[mt][1].y);
                unsigned al2 = __float_as_uint(af[mt][2].y), al3 = __float_as_uint(af[mt][3].y);
#pragma unroll
                for (int nt = 0; nt < 4; nt++) {
                    unsigned bh0 = __float_as_uint(bf[nt][0].x), bh1 = __float_as_uint(bf[nt][1].x);
                    unsigned bl0 = __float_as_uint(bf[nt][0].y), bl1 = __float_as_uint(bf[nt][1].y);
                    mma_tf32(acc[mt][nt], ah0, ah1, ah2, ah3, bh0, bh1);
                    mma_tf32(acc[mt][nt], ah0, ah1, ah2, ah3, bl0, bl1);
                    mma_tf32(acc[mt][nt], al0, al1, al2, al3, bh0, bh1);
                }
            }
        }
        __syncthreads();  // done reading Bs before next tile overwrite

        // ---- epilogue for this n-tile ----
#pragma unroll
        for (int mt = 0; mt < 2; mt++) {
#pragma unroll
            for (int nt = 0; nt < 4; nt++) {
                int col = nb + wn + nt * 8 + 2 * tg;
                float bx = 0.f, by = 0.f;
                if (bias) { bx = bias[col]; by = bias[col + 1]; }
                int row0 = bm + wm + mt * 16 + gr;
                int row1 = row0 + 8;
                float2 v0 = make_float2(acc[mt][nt][0] + bx, acc[mt][nt][1] + by);
                float2 v1 = make_float2(acc[mt][nt][2] + bx, acc[mt][nt][3] + by);
                if (relu) {
                    v0.x = fmaxf(v0.x, 0.f); v0.y = fmaxf(v0.y, 0.f);
                    v1.x = fmaxf(v1.x, 0.f); v1.y = fmaxf(v1.y, 0.f);
                }
                if (row0 < M) *(float2*)(C + (size_t)row0 * NOUT + col) = v0;
                if (row1 < M) *(float2*)(C + (size_t)row1 * NOUT + col) = v1;
            }
        }
    }
}

// ---------------- GRU elementwise; gh==nullptr means hprev was 0 -> gh gates = bhh ----------------
__global__ void k_gru(const float* __restrict__ gi, const float* __restrict__ gh,
                      const float* __restrict__ bhh, float* __restrict__ h)
{
    int idx = blockIdx.x * blockDim.x + threadIdx.x;  // node*32 + g
    if (idx >= N_NODE * 32) return;
    int n = idx >> 5, g = idx & 31;
    const float4* gi4 = (const float4*)(gi + (size_t)n * 384);
    float4 ir = gi4[g], iz = gi4[32 + g], in_ = gi4[64 + g];
    float4 hr, hz, hn;
    if (gh) {
        const float4* gh4 = (const float4*)(gh + (size_t)n * 384);
        hr = gh4[g]; hz = gh4[32 + g]; hn = gh4[64 + g];
    } else {
        const float4* b4 = (const float4*)bhh;
        hr = b4[g]; hz = b4[32 + g]; hn = b4[64 + g];
    }
    float4 h0 = ((const float4*)h)[(size_t)n * 32 + g];
    float4 out;
    {
        float r = sigmoidf_(ir.x + hr.x), z = sigmoidf_(iz.x + hz.x);
        float nn = tanhf(in_.x + r * hn.x);
        out.x = (1.f - z) * nn + z * h0.x;
    }
    {
        float r = sigmoidf_(ir.y + hr.y), z = sigmoidf_(iz.y + hz.y);
        float nn = tanhf(in_.y + r * hn.y);
        out.y = (1.f - z) * nn + z * h0.y;
    }
    {
        float r = sigmoidf_(ir.z + hr.z), z = sigmoidf_(iz.z + hz.z);
        float nn = tanhf(in_.z + r * hn.z);
        out.z = (1.f - z) * nn + z * h0.z;
    }
    {
        float r = sigmoidf_(ir.w + hr.w), z = sigmoidf_(iz.w + hz.w);
        float nn = tanhf(in_.w + r * hn.w);
        out.w = (1.f - z) * nn + z * h0.w;
    }
    ((float4*)h)[(size_t)n * 32 + g] = out;
}

// ---------------- output scatter: deterministic last-index-wins on collisions ----------------
__global__ void k_scat1(const int* __restrict__ nb, const int* __restrict__ ne,
                        int* __restrict__ winner, int n_ent)
{
    int n = blockIdx.x * blockDim.x + threadIdx.x;
    if (n >= N_NODE) return;
    size_t slot = (size_t)nb[n] * n_ent + ne[n];
    atomicMax(&winner[slot], n);
}

__global__ void k_scat2(const float* __restrict__ h, const float* __restrict__ Wfinal,
                        const int* __restrict__ nb, const int* __restrict__ ne,
                        const int* __restrict__ winner, float* __restrict__ out, int n_ent)
{
    int n = (int)((blockIdx.x * blockDim.x + threadIdx.x) >> 5);
    int lane = threadIdx.x & 31;
    if (n >= N_NODE) return;
    float4 hv = ((const float4*)h)[(size_t)n * 32 + lane];
    float4 wv = ((const float4*)Wfinal)[lane];
    float s = hv.x * wv.x + hv.y * wv.y + hv.z * wv.z + hv.w * wv.w;
#pragma unroll
    for (int off = 16; off; off >>= 1) s += __shfl_xor_sync(0xffffffffu, s, off);
    if (lane == 0) {
        size_t slot = (size_t)nb[n] * n_ent + ne[n];
        if (winner[slot] == n) out[slot] = s;
    }
}

// ---------------- host launcher ----------------
extern "C" void kernel_launch(void* const* d_in, const int* in_sizes, int n_in,
                              void* d_out, int out_size)
{
    const float* rela     = (const float*)d_in[0];
    const float* Ws       = (const float*)d_in[1];
    const float* Wr       = (const float*)d_in[2];
    const float* Wqr_w    = (const float*)d_in[3];
    const float* Wqr_b    = (const float*)d_in[4];
    const float* Wtau     = (const float*)d_in[5];
    const float* walpha_w = (const float*)d_in[6];
    const float* walpha_b = (const float*)d_in[7];
    const float* Wh       = (const float*)d_in[8];
    const float* wt1      = (const float*)d_in[9];
    const float* bt1      = (const float*)d_in[10];
    const float* wt2      = (const float*)d_in[11];
    const float* bt2      = (const float*)d_in[12];
    const float* Wih      = (const float*)d_in[13];
    const float* Whh      = (const float*)d_in[14];
    const float* bih      = (const float*)d_in[15];
    const float* bhh      = (const float*)d_in[16];
    const float* Wfinal   = (const float*)d_in[17];
    const int*   q_rel    = (const int*)d_in[18];
    const int*   q_tau    = (const int*)d_in[19];
    const int*   e_ridx   = (const int*)d_in[20];
    const int*   e_rel    = (const int*)d_in[21];
    const int*   e_tau    = (const int*)d_in[22];
    const int*   e_sub    = (const int*)d_in[23];
    const int*   e_obj    = (const int*)d_in[24];
    const int*   nb       = (const int*)d_in[25];
    const int*   ne       = (const int*)d_in[26];

    int nq    = in_sizes[18];
    int n_ent = out_size / nq;

    float *hprev, *hidden1, *agg, *gi, *gh, *HS, *Rattn, *Qattn, *Hattn, *Hmsg;
    int* winner;
    cudaGetSymbolAddress((void**)&hprev,   g_hprev);
    cudaGetSymbolAddress((void**)&hidden1, g_hidden1);
    cudaGetSymbolAddress((void**)&agg,     g_agg);
    cudaGetSymbolAddress((void**)&gi,      g_gi);
    cudaGetSymbolAddress((void**)&gh,      g_gh);
    cudaGetSymbolAddress((void**)&HS,      g_HS);
    cudaGetSymbolAddress((void**)&Rattn,   g_Rattn);
    cudaGetSymbolAddress((void**)&Qattn,   g_Qattn);
    cudaGetSymbolAddress((void**)&Hattn,   g_Hattn);
    cudaGetSymbolAddress((void**)&Hmsg,    g_Hmsg);
    cudaGetSymbolAddress((void**)&winner,  g_winner);

    cudaFuncSetAttribute(k_mma, cudaFuncAttributeMaxDynamicSharedMemorySize, SMEM_MMA);

    cudaMemsetAsync(hprev, 0, sizeof(float) * (size_t)N_NODE * D_DIM);
    cudaMemsetAsync(HS,    0, sizeof(float) * (size_t)N_NODE * A_DIM);  // layer-0: hprev@Ws^T == 0

    const int mblocks = (N_NODE + 127) / 128;   // 782

    for (int l = 0; l < L_LAYERS; l++) {
        cudaMemsetAsync(agg, 0, sizeof(float) * (size_t)N_NODE * D_DIM);

        k_tab_rq<<<NREL + NQ_C, 64>>>(rela + (size_t)l * NREL * 128,
                                      Wr + (size_t)l * 64 * 128,
                                      Wqr_w + (size_t)l * 64 * 128,
                                      Wqr_b + (size_t)l * 64,
                                      q_rel, Rattn, Qattn);
        k_tab_delta<<<N_DELTA, 128>>>(wt1 + (size_t)l * 128, bt1 + (size_t)l * 128,
                                      wt2 + (size_t)l * 128, bt2 + (size_t)l * 128,
                                      Wtau + (size_t)l * 64 * 128, Hmsg, Hattn);
        if (l > 0) {
            // HS = hprev @ Ws^T  [N_NODE, 64]   (layer 0: hprev==0 -> HS memset above)
            k_mma<<<mblocks, 256, SMEM_MMA>>>(hprev, Ws + (size_t)l * 64 * 128,
                                              nullptr, HS, N_NODE, 64, 0);
        }

        k_edge<<<N_EDGE / 8, 256>>>(e_sub + (size_t)l * N_EDGE, e_rel + (size_t)l * N_EDGE,
                                    e_obj + (size_t)l * N_EDGE, e_ridx + (size_t)l * N_EDGE,
                                    e_tau + (size_t)l * N_EDGE, q_tau,
                                    HS, Rattn, Qattn, Hattn, Hmsg, hprev,
                                    rela + (size_t)l * NREL * 128,
                                    walpha_w + (size_t)l * 64, walpha_b + l, agg);

        // hidden1 = relu(agg @ Wh^T)
        k_mma<<<mblocks, 256, SMEM_MMA>>>(agg, Wh + (size_t)l * 128 * 128,
                                          nullptr, hidden1, N_NODE, 128, 1);
        // gi = hidden1 @ Wih^T + bih
        k_mma<<<mblocks, 256, SMEM_MMA>>>(hidden1, Wih + (size_t)l * 384 * 128,
                                          bih + (size_t)l * 384, gi, N_NODE, 384, 0);
        if (l > 0) {
            // gh = hprev @ Whh^T + bhh
            k_mma<<<mblocks, 256, SMEM_MMA>>>(hprev, Whh + (size_t)l * 384 * 128,
                                              bhh + (size_t)l * 384, gh, N_NODE, 384, 0);
        }
        // hprev <- GRU   (layer 0: gh gates are just bhh since hprev==0)
        k_gru<<<(N_NODE * 32) / 256, 256>>>(gi, (l > 0) ? gh : nullptr,
                                            bhh + (size_t)l * 384, hprev);
    }

    cudaMemsetAsync(d_out, 0, (size_t)out_size * sizeof(float));
    cudaMemsetAsync(winner, 0xFF, (size_t)out_size * sizeof(int));
    k_scat1<<<(N_NODE + 255) / 256, 256>>>(nb, ne, winner, n_ent);
    k_scat2<<<(N_NODE * 32) / 256, 256>>>(hprev, Wfinal, nb, ne, winner, (float*)d_out, n_ent);
}

// round 6
// speedup vs baseline: 2.9555x; 1.4047x over previous
#include <cuda_runtime.h>
#include <math.h>

#define L_LAYERS 3
#define D_DIM    128
#define A_DIM    64
#define NREL     401
#define N_NODE   100000
#define N_EDGE   600000
#define NQ_C     512
#define N_DELTA  731
#define MAX_OUT  (512*50000)

// k_mma smem: As[128][132] fp32 + Bs[64][132] fp32  (101,376 B -> 2 CTAs/SM)
#define MMA_STRIDE 132
#define SMEM_MMA   ((128 + 64) * MMA_STRIDE * 4)

// ---------------- static device scratch (no allocations allowed) ----------------
__device__ float g_hprev  [N_NODE * D_DIM];
__device__ float g_hidden1[N_NODE * D_DIM];
__device__ float g_agg    [N_NODE * D_DIM];
__device__ float g_gi     [N_NODE * 3 * D_DIM];
__device__ float g_gh     [N_NODE * 3 * D_DIM];
__device__ float g_HS     [N_NODE * A_DIM];
__device__ float g_Rattn  [NREL * A_DIM];
__device__ float g_Qattn  [NQ_C * A_DIM];
__device__ float g_Hattn  [N_DELTA * A_DIM];
__device__ float g_Hmsg   [N_DELTA * D_DIM];
__device__ int   g_winner [MAX_OUT];

__device__ __forceinline__ float sigmoidf_(float x) { return 1.0f / (1.0f + expf(-x)); }

// register split fp32 -> (tf32 hi, tf32 lo)
__device__ __forceinline__ void tsplit(float x, unsigned& h, unsigned& l) {
    asm("cvt.rna.tf32.f32 %0, %1;" : "=r"(h) : "f"(x));
    float lf = x - __uint_as_float(h);
    asm("cvt.rna.tf32.f32 %0, %1;" : "=r"(l) : "f"(lf));
}

__device__ __forceinline__ void mma_tf32(float* c,
                                         unsigned a0, unsigned a1, unsigned a2, unsigned a3,
                                         unsigned b0, unsigned b1) {
    asm volatile(
        "mma.sync.aligned.m16n8k8.row.col.f32.tf32.tf32.f32 "
        "{%0,%1,%2,%3}, {%4,%5,%6,%7}, {%8,%9}, {%0,%1,%2,%3};"
        : "+f"(c[0]), "+f"(c[1]), "+f"(c[2]), "+f"(c[3])
        : "r"(a0), "r"(a1), "r"(a2), "r"(a3), "r"(b0), "r"(b1));
}

// ---------------- per-relation / per-query attention tables ----------------
__global__ void k_tab_rq(const float* __restrict__ rela_l,
                         const float* __restrict__ Wr_l,
                         const float* __restrict__ Wqr_w_l,
                         const float* __restrict__ Wqr_b_l,
                         const int*   __restrict__ q_rel,
                         float* __restrict__ Rattn,
                         float* __restrict__ Qattn)
{
    __shared__ float hv[128];
    int b = blockIdx.x;
    int a = threadIdx.x; // 0..63
    const float* src = (b < NREL) ? (rela_l + (size_t)b * 128)
                                  : (rela_l + (size_t)q_rel[b - NREL] * 128);
    hv[a] = src[a];
    hv[a + 64] = src[a + 64];
    __syncthreads();
    const float* W = ((b < NREL) ? Wr_l : Wqr_w_l) + (size_t)a * 128;
    float s = 0.f;
#pragma unroll
    for (int k = 0; k < 128; k += 4) {
        float4 w = *(const float4*)(W + k);
        s += hv[k] * w.x + hv[k + 1] * w.y + hv[k + 2] * w.z + hv[k + 3] * w.w;
    }
    if (b < NREL) Rattn[b * 64 + a] = s;
    else          Qattn[(b - NREL) * 64 + a] = s + Wqr_b_l[a];
}

// ---------------- per-delta tables: h_hau vector + h_hau @ Wtau^T ----------------
__global__ void k_tab_delta(const float* __restrict__ wt1, const float* __restrict__ bt1,
                            const float* __restrict__ wt2, const float* __restrict__ bt2,
                            const float* __restrict__ Wtau_l,
                            float* __restrict__ Hmsg, float* __restrict__ Hattn)
{
    __shared__ float hh[128];
    int di = blockIdx.x;           // 0..730
    float delta = (float)(di - 365);
    int d = threadIdx.x;           // 0..127
    float v = wt1[d] * delta + bt1[d] + sinf(wt2[d] * delta + bt2[d]);
    hh[d] = v;
    Hmsg[(size_t)di * 128 + d] = v;
    __syncthreads();
    if (d < 64) {
        const float* W = Wtau_l + (size_t)d * 128;
        float s = 0.f;
#pragma unroll
        for (int k = 0; k < 128; k += 4) {
            float4 w = *(const float4*)(W + k);
            s += hh[k] * w.x + hh[k + 1] * w.y + hh[k + 2] * w.z + hh[k + 3] * w.w;
        }
        Hattn[(size_t)di * 64 + d] = s;
    }
}

// ---------------- edge kernel: one warp per edge ----------------
__global__ void __launch_bounds__(256) k_edge(
    const int* __restrict__ e_sub, const int* __restrict__ e_rel,
    const int* __restrict__ e_obj, const int* __restrict__ e_ridx,
    const int* __restrict__ e_tau, const int* __restrict__ q_tau,
    const float* __restrict__ HS, const float* __restrict__ Rattn,
    const float* __restrict__ Qattn, const float* __restrict__ Hattn,
    const float* __restrict__ Hmsg, const float* __restrict__ hprev,
    const float* __restrict__ rela_l, const float* __restrict__ walpha_w_l,
    const float* __restrict__ walpha_b_l, float* __restrict__ agg)
{
    int e = (int)((blockIdx.x * blockDim.x + threadIdx.x) >> 5);
    int lane = threadIdx.x & 31;
    if (e >= N_EDGE) return;

    int s_ = e_sub[e];
    int r_ = e_rel[e];
    int o_ = e_obj[e];
    int q_ = e_ridx[e];
    int t_ = e_tau[e];
    int tq = q_tau[q_];
    int tau = (t_ >= 0) ? t_ : tq;
    int di = tau - tq + 365;
    di = min(max(di, 0), 730);

    float2 hs2 = ((const float2*)HS)   [(size_t)s_ * 32 + lane];
    float2 rr2 = ((const float2*)Rattn)[(size_t)r_ * 32 + lane];
    float2 qq2 = ((const float2*)Qattn)[(size_t)q_ * 32 + lane];
    float2 tt2 = ((const float2*)Hattn)[(size_t)di * 32 + lane];
    float vx = fmaxf(hs2.x + rr2.x + qq2.x + tt2.x, 0.f);
    float vy = fmaxf(hs2.y + rr2.y + qq2.y + tt2.y, 0.f);
    float2 wa = ((const float2*)walpha_w_l)[lane];
    float acc = vx * wa.x + vy * wa.y;
#pragma unroll
    for (int off = 16; off; off >>= 1) acc += __shfl_xor_sync(0xffffffffu, acc, off);
    float alpha = 1.0f / (1.0f + expf(-(acc + walpha_b_l[0])));

    float4 h4 = ((const float4*)hprev) [(size_t)s_ * 32 + lane];
    float4 r4 = ((const float4*)rela_l)[(size_t)r_ * 32 + lane];
    float4 m4 = ((const float4*)Hmsg)  [(size_t)di * 32 + lane];
    float mx = alpha * (h4.x + r4.x + m4.x);
    float my = alpha * (h4.y + r4.y + m4.y);
    float mz = alpha * (h4.z + r4.z + m4.z);
    float mw = alpha * (h4.w + r4.w + m4.w);
    float* dst = agg + (size_t)o_ * 128 + lane * 4;
    asm volatile("red.global.add.v4.f32 [%0], {%1,%2,%3,%4};"
                 :: "l"(dst), "f"(mx), "f"(my), "f"(mz), "f"(mw) : "memory");
}

// ---------------- tensor-core GEMM v2: fp32 smem + register tf32 split ----------------
// C[M,NOUT] = A[M,128] @ W[NOUT,128]^T (+bias)(+relu), NOUT multiple of 64.
// 256 thr = 8 warps (4m x 2n), BM=128, n-tiles of 64 looped internally.
// blockIdx.y==1 selects the second (independent) problem -> gi/gh batched.
__global__ void __launch_bounds__(256, 2) k_mma(
    const float* __restrict__ A, const float* __restrict__ W,
    const float* __restrict__ bias, float* __restrict__ C,
    const float* __restrict__ A2, const float* __restrict__ W2,
    const float* __restrict__ bias2, float* __restrict__ C2,
    int M, int NOUT, int relu)
{
    if (blockIdx.y == 1) { A = A2; W = W2; bias = bias2; C = C2; }
    extern __shared__ float sm[];
    float* As = sm;                        // [128][MMA_STRIDE]
    float* Bs = sm + 128 * MMA_STRIDE;     // [64][MMA_STRIDE]

    int tid  = threadIdx.x;
    int bm   = blockIdx.x * 128;
    int lane = tid & 31;
    int warp = tid >> 5;
    int wm   = (warp & 3) * 32;   // 0,32,64,96
    int wn   = (warp >> 2) * 32;  // 0,32
    int gr   = lane >> 2;         // 0..7
    int tg   = lane & 3;          // 0..3

    // ---- load A tile (128 x 128) fp32 ----
    for (int i = tid; i < 128 * 32; i += 256) {
        int row = i >> 5;
        int c4  = (i & 31) * 4;
        int grow = bm + row;
        float4 v = (grow < M) ? *(const float4*)(A + (size_t)grow * 128 + c4)
                              : make_float4(0.f, 0.f, 0.f, 0.f);
        *(float4*)(As + row * MMA_STRIDE + c4) = v;
    }
    __syncthreads();

    for (int nb = 0; nb < NOUT; nb += 64) {
        // ---- load B tile (64 x 128) fp32 ----
        for (int i = tid; i < 64 * 32; i += 256) {
            int row = i >> 5;
            int c4  = (i & 31) * 4;
            float4 v = *(const float4*)(W + (size_t)(nb + row) * 128 + c4);
            *(float4*)(Bs + row * MMA_STRIDE + c4) = v;
        }
        __syncthreads();

        float acc[2][4][4];
#pragma unroll
        for (int mt = 0; mt < 2; mt++)
#pragma unroll
            for (int nt = 0; nt < 4; nt++)
#pragma unroll
                for (int r = 0; r < 4; r++) acc[mt][nt][r] = 0.f;

#pragma unroll
        for (int kk = 0; kk < 128; kk += 8) {
            unsigned ah[2][4], al[2][4];
#pragma unroll
            for (int mt = 0; mt < 2; mt++) {
                const float* ap = As + (wm + mt * 16 + gr) * MMA_STRIDE + kk + tg;
                float a0 = ap[0];
                float a1 = ap[8 * MMA_STRIDE];
                float a2 = ap[4];
                float a3 = ap[8 * MMA_STRIDE + 4];
                tsplit(a0, ah[mt][0], al[mt][0]);
                tsplit(a1, ah[mt][1], al[mt][1]);
                tsplit(a2, ah[mt][2], al[mt][2]);
                tsplit(a3, ah[mt][3], al[mt][3]);
            }
            unsigned bh[4][2], bl[4][2];
#pragma unroll
            for (int nt = 0; nt < 4; nt++) {
                const float* bp = Bs + (wn + nt * 8 + gr) * MMA_STRIDE + kk + tg;
                float b0 = bp[0];
                float b1 = bp[4];
                tsplit(b0, bh[nt][0], bl[nt][0]);
                tsplit(b1, bh[nt][1], bl[nt][1]);
            }
#pragma unroll
            for (int mt = 0; mt < 2; mt++)
#pragma unroll
                for (int nt = 0; nt < 4; nt++) {
                    mma_tf32(acc[mt][nt], ah[mt][0], ah[mt][1], ah[mt][2], ah[mt][3],
                             bh[nt][0], bh[nt][1]);
                    mma_tf32(acc[mt][nt], ah[mt][0], ah[mt][1], ah[mt][2], ah[mt][3],
                             bl[nt][0], bl[nt][1]);
                    mma_tf32(acc[mt][nt], al[mt][0], al[mt][1], al[mt][2], al[mt][3],
                             bh[nt][0], bh[nt][1]);
                }
        }
        __syncthreads();  // done reading Bs before next tile overwrite

        // ---- epilogue for this n-tile ----
#pragma unroll
        for (int mt = 0; mt < 2; mt++) {
#pragma unroll
            for (int nt = 0; nt < 4; nt++) {
                int col = nb + wn + nt * 8 + 2 * tg;
                float bx = 0.f, by = 0.f;
                if (bias) { bx = bias[col]; by = bias[col + 1]; }
                int row0 = bm + wm + mt * 16 + gr;
                int row1 = row0 + 8;
                float2 v0 = make_float2(acc[mt][nt][0] + bx, acc[mt][nt][1] + by);
                float2 v1 = make_float2(acc[mt][nt][2] + bx, acc[mt][nt][3] + by);
                if (relu) {
                    v0.x = fmaxf(v0.x, 0.f); v0.y = fmaxf(v0.y, 0.f);
                    v1.x = fmaxf(v1.x, 0.f); v1.y = fmaxf(v1.y, 0.f);
                }
                if (row0 < M) *(float2*)(C + (size_t)row0 * NOUT + col) = v0;
                if (row1 < M) *(float2*)(C + (size_t)row1 * NOUT + col) = v1;
            }
        }
    }
}

// ---------------- GRU elementwise; gh==nullptr means hprev was 0 -> gh gates = bhh ----------------
__global__ void k_gru(const float* __restrict__ gi, const float* __restrict__ gh,
                      const float* __restrict__ bhh, float* __restrict__ h)
{
    int idx = blockIdx.x * blockDim.x + threadIdx.x;  // node*32 + g
    if (idx >= N_NODE * 32) return;
    int n = idx >> 5, g = idx & 31;
    const float4* gi4 = (const float4*)(gi + (size_t)n * 384);
    float4 ir = gi4[g], iz = gi4[32 + g], in_ = gi4[64 + g];
    float4 hr, hz, hn;
    if (gh) {
        const float4* gh4 = (const float4*)(gh + (size_t)n * 384);
        hr = gh4[g]; hz = gh4[32 + g]; hn = gh4[64 + g];
    } else {
        const float4* b4 = (const float4*)bhh;
        hr = b4[g]; hz = b4[32 + g]; hn = b4[64 + g];
    }
    float4 h0 = ((const float4*)h)[(size_t)n * 32 + g];
    float4 out;
    {
        float r = sigmoidf_(ir.x + hr.x), z = sigmoidf_(iz.x + hz.x);
        float nn = tanhf(in_.x + r * hn.x);
        out.x = (1.f - z) * nn + z * h0.x;
    }
    {
        float r = sigmoidf_(ir.y + hr.y), z = sigmoidf_(iz.y + hz.y);
        float nn = tanhf(in_.y + r * hn.y);
        out.y = (1.f - z) * nn + z * h0.y;
    }
    {
        float r = sigmoidf_(ir.z + hr.z), z = sigmoidf_(iz.z + hz.z);
        float nn = tanhf(in_.z + r * hn.z);
        out.z = (1.f - z) * nn + z * h0.z;
    }
    {
        float r = sigmoidf_(ir.w + hr.w), z = sigmoidf_(iz.w + hz.w);
        float nn = tanhf(in_.w + r * hn.w);
        out.w = (1.f - z) * nn + z * h0.w;
    }
    ((float4*)h)[(size_t)n * 32 + g] = out;
}

// ---------------- output scatter: deterministic last-index-wins on collisions ----------------
__global__ void k_scat1(const int* __restrict__ nb, const int* __restrict__ ne,
                        int* __restrict__ winner, int n_ent)
{
    int n = blockIdx.x * blockDim.x + threadIdx.x;
    if (n >= N_NODE) return;
    size_t slot = (size_t)nb[n] * n_ent + ne[n];
    atomicMax(&winner[slot], n);
}

__global__ void k_scat2(const float* __restrict__ h, const float* __restrict__ Wfinal,
                        const int* __restrict__ nb, const int* __restrict__ ne,
                        const int* __restrict__ winner, float* __restrict__ out, int n_ent)
{
    int n = (int)((blockIdx.x * blockDim.x + threadIdx.x) >> 5);
    int lane = threadIdx.x & 31;
    if (n >= N_NODE) return;
    float4 hv = ((const float4*)h)[(size_t)n * 32 + lane];
    float4 wv = ((const float4*)Wfinal)[lane];
    float s = hv.x * wv.x + hv.y * wv.y + hv.z * wv.z + hv.w * wv.w;
#pragma unroll
    for (int off = 16; off; off >>= 1) s += __shfl_xor_sync(0xffffffffu, s, off);
    if (lane == 0) {
        size_t slot = (size_t)nb[n] * n_ent + ne[n];
        if (winner[slot] == n) out[slot] = s;
    }
}

// ---------------- host launcher ----------------
extern "C" void kernel_launch(void* const* d_in, const int* in_sizes, int n_in,
                              void* d_out, int out_size)
{
    const float* rela     = (const float*)d_in[0];
    const float* Ws       = (const float*)d_in[1];
    const float* Wr       = (const float*)d_in[2];
    const float* Wqr_w    = (const float*)d_in[3];
    const float* Wqr_b    = (const float*)d_in[4];
    const float* Wtau     = (const float*)d_in[5];
    const float* walpha_w = (const float*)d_in[6];
    const float* walpha_b = (const float*)d_in[7];
    const float* Wh       = (const float*)d_in[8];
    const float* wt1      = (const float*)d_in[9];
    const float* bt1      = (const float*)d_in[10];
    const float* wt2      = (const float*)d_in[11];
    const float* bt2      = (const float*)d_in[12];
    const float* Wih      = (const float*)d_in[13];
    const float* Whh      = (const float*)d_in[14];
    const float* bih      = (const float*)d_in[15];
    const float* bhh      = (const float*)d_in[16];
    const float* Wfinal   = (const float*)d_in[17];
    const int*   q_rel    = (const int*)d_in[18];
    const int*   q_tau    = (const int*)d_in[19];
    const int*   e_ridx   = (const int*)d_in[20];
    const int*   e_rel    = (const int*)d_in[21];
    const int*   e_tau    = (const int*)d_in[22];
    const int*   e_sub    = (const int*)d_in[23];
    const int*   e_obj    = (const int*)d_in[24];
    const int*   nb       = (const int*)d_in[25];
    const int*   ne       = (const int*)d_in[26];

    int nq    = in_sizes[18];
    int n_ent = out_size / nq;

    float *hprev, *hidden1, *agg, *gi, *gh, *HS, *Rattn, *Qattn, *Hattn, *Hmsg;
    int* winner;
    cudaGetSymbolAddress((void**)&hprev,   g_hprev);
    cudaGetSymbolAddress((void**)&hidden1, g_hidden1);
    cudaGetSymbolAddress((void**)&agg,     g_agg);
    cudaGetSymbolAddress((void**)&gi,      g_gi);
    cudaGetSymbolAddress((void**)&gh,      g_gh);
    cudaGetSymbolAddress((void**)&HS,      g_HS);
    cudaGetSymbolAddress((void**)&Rattn,   g_Rattn);
    cudaGetSymbolAddress((void**)&Qattn,   g_Qattn);
    cudaGetSymbolAddress((void**)&Hattn,   g_Hattn);
    cudaGetSymbolAddress((void**)&Hmsg,    g_Hmsg);
    cudaGetSymbolAddress((void**)&winner,  g_winner);

    cudaFuncSetAttribute(k_mma, cudaFuncAttributeMaxDynamicSharedMemorySize, SMEM_MMA);

    cudaMemsetAsync(hprev, 0, sizeof(float) * (size_t)N_NODE * D_DIM);
    cudaMemsetAsync(HS,    0, sizeof(float) * (size_t)N_NODE * A_DIM);  // layer-0: hprev@Ws^T == 0

    const int mblocks = (N_NODE + 127) / 128;   // 782
    dim3 g1(mblocks, 1), g2(mblocks, 2);

    for (int l = 0; l < L_LAYERS; l++) {
        cudaMemsetAsync(agg, 0, sizeof(float) * (size_t)N_NODE * D_DIM);

        k_tab_rq<<<NREL + NQ_C, 64>>>(rela + (size_t)l * NREL * 128,
                                      Wr + (size_t)l * 64 * 128,
                                      Wqr_w + (size_t)l * 64 * 128,
                                      Wqr_b + (size_t)l * 64,
                                      q_rel, Rattn, Qattn);
        k_tab_delta<<<N_DELTA, 128>>>(wt1 + (size_t)l * 128, bt1 + (size_t)l * 128,
                                      wt2 + (size_t)l * 128, bt2 + (size_t)l * 128,
                                      Wtau + (size_t)l * 64 * 128, Hmsg, Hattn);
        if (l > 0) {
            // HS = hprev @ Ws^T  [N_NODE, 64]   (layer 0: hprev==0 -> HS memset above)
            k_mma<<<g1, 256, SMEM_MMA>>>(hprev, Ws + (size_t)l * 64 * 128, nullptr, HS,
                                         nullptr, nullptr, nullptr, nullptr,
                                         N_NODE, 64, 0);
        }

        k_edge<<<N_EDGE / 8, 256>>>(e_sub + (size_t)l * N_EDGE, e_rel + (size_t)l * N_EDGE,
                                    e_obj + (size_t)l * N_EDGE, e_ridx + (size_t)l * N_EDGE,
                                    e_tau + (size_t)l * N_EDGE, q_tau,
                                    HS, Rattn, Qattn, Hattn, Hmsg, hprev,
                                    rela + (size_t)l * NREL * 128,
                                    walpha_w + (size_t)l * 64, walpha_b + l, agg);

        // hidden1 = relu(agg @ Wh^T)
        k_mma<<<g1, 256, SMEM_MMA>>>(agg, Wh + (size_t)l * 128 * 128, nullptr, hidden1,
                                     nullptr, nullptr, nullptr, nullptr,
                                     N_NODE, 128, 1);
        if (l > 0) {
            // batched: y=0 -> gi = hidden1@Wih^T+bih ; y=1 -> gh = hprev@Whh^T+bhh
            k_mma<<<g2, 256, SMEM_MMA>>>(hidden1, Wih + (size_t)l * 384 * 128,
                                         bih + (size_t)l * 384, gi,
                                         hprev, Whh + (size_t)l * 384 * 128,
                                         bhh + (size_t)l * 384, gh,
                                         N_NODE, 384, 0);
        } else {
            k_mma<<<g1, 256, SMEM_MMA>>>(hidden1, Wih + (size_t)l * 384 * 128,
                                         bih + (size_t)l * 384, gi,
                                         nullptr, nullptr, nullptr, nullptr,
                                         N_NODE, 384, 0);
        }
        // hprev <- GRU   (layer 0: gh gates are just bhh since hprev==0)
        k_gru<<<(N_NODE * 32) / 256, 256>>>(gi, (l > 0) ? gh : nullptr,
                                            bhh + (size_t)l * 384, hprev);
    }

    cudaMemsetAsync(d_out, 0, (size_t)out_size * sizeof(float));
    cudaMemsetAsync(winner, 0xFF, (size_t)out_size * sizeof(int));
    k_scat1<<<(N_NODE + 255) / 256, 256>>>(nb, ne, winner, n_ent);
    k_scat2<<<(N_NODE * 32) / 256, 256>>>(hprev, Wfinal, nb, ne, winner, (float*)d_out, n_ent);
}

// round 7
// speedup vs baseline: 3.7463x; 1.2675x over previous
#include <cuda_runtime.h>
#include <cuda_bf16.h>
#include <math.h>

#define L_LAYERS 3
#define D_DIM    128
#define A_DIM    64
#define NREL     401
#define N_NODE   100000
#define N_EDGE   600000
#define NQ_C     512
#define N_DELTA  731
#define MAX_OUT  (512*50000)

// k_mma smem: 4 bf16x2-packed planes, stride 68 words (64 k-pairs + pad, mod32=4)
#define AST 68
#define SMEM_MMA ((128 + 128 + 64 + 64) * AST * 4)   // 104448 B -> 2 CTAs/SM

// ---------------- static device scratch (no allocations allowed) ----------------
__device__ float g_hprev  [N_NODE * D_DIM];
__device__ float g_hidden1[N_NODE * D_DIM];
__device__ float g_agg    [N_NODE * D_DIM];
__device__ float g_gi     [N_NODE * 3 * D_DIM];
__device__ float g_gh     [N_NODE * 3 * D_DIM];
__device__ float g_HS     [N_NODE * A_DIM];
__device__ float g_Rattn  [NREL * A_DIM];
__device__ float g_Qattn  [NQ_C * A_DIM];
__device__ float g_Hattn  [N_DELTA * A_DIM];
__device__ float g_Hmsg   [N_DELTA * D_DIM];
__device__ int   g_winner [MAX_OUT];

__device__ __forceinline__ float sigmoidf_(float x) { return 1.0f / (1.0f + expf(-x)); }

// pack two fp32 into one bf16x2 word: low half = x0 (k even), high half = x1 (k+1)
__device__ __forceinline__ unsigned pack_bf2(float x0, float x1) {
    unsigned r;
    asm("cvt.rn.bf16x2.f32 %0, %1, %2;" : "=r"(r) : "f"(x1), "f"(x0));
    return r;
}
// split a pair of fp32 into (hi bf16x2 word, lo bf16x2 word)
__device__ __forceinline__ void split_pair(float x0, float x1, unsigned& h, unsigned& l) {
    h = pack_bf2(x0, x1);
    float h0 = __uint_as_float(h << 16);
    float h1 = __uint_as_float(h & 0xFFFF0000u);
    l = pack_bf2(x0 - h0, x1 - h1);
}

__device__ __forceinline__ void mma_bf16(float* c,
                                         unsigned a0, unsigned a1, unsigned a2, unsigned a3,
                                         unsigned b0, unsigned b1) {
    asm volatile(
        "mma.sync.aligned.m16n8k16.row.col.f32.bf16.bf16.f32 "
        "{%0,%1,%2,%3}, {%4,%5,%6,%7}, {%8,%9}, {%0,%1,%2,%3};"
        : "+f"(c[0]), "+f"(c[1]), "+f"(c[2]), "+f"(c[3])
        : "r"(a0), "r"(a1), "r"(a2), "r"(a3), "r"(b0), "r"(b1));
}

// ---------------- per-relation / per-query attention tables ----------------
__global__ void k_tab_rq(const float* __restrict__ rela_l,
                         const float* __restrict__ Wr_l,
                         const float* __restrict__ Wqr_w_l,
                         const float* __restrict__ Wqr_b_l,
                         const int*   __restrict__ q_rel,
                         float* __restrict__ Rattn,
                         float* __restrict__ Qattn)
{
    __shared__ float hv[128];
    int b = blockIdx.x;
    int a = threadIdx.x; // 0..63
    const float* src = (b < NREL) ? (rela_l + (size_t)b * 128)
                                  : (rela_l + (size_t)q_rel[b - NREL] * 128);
    hv[a] = src[a];
    hv[a + 64] = src[a + 64];
    __syncthreads();
    const float* W = ((b < NREL) ? Wr_l : Wqr_w_l) + (size_t)a * 128;
    float s = 0.f;
#pragma unroll
    for (int k = 0; k < 128; k += 4) {
        float4 w = *(const float4*)(W + k);
        s += hv[k] * w.x + hv[k + 1] * w.y + hv[k + 2] * w.z + hv[k + 3] * w.w;
    }
    if (b < NREL) Rattn[b * 64 + a] = s;
    else          Qattn[(b - NREL) * 64 + a] = s + Wqr_b_l[a];
}

// ---------------- per-delta tables: h_hau vector + h_hau @ Wtau^T ----------------
__global__ void k_tab_delta(const float* __restrict__ wt1, const float* __restrict__ bt1,
                            const float* __restrict__ wt2, const float* __restrict__ bt2,
                            const float* __restrict__ Wtau_l,
                            float* __restrict__ Hmsg, float* __restrict__ Hattn)
{
    __shared__ float hh[128];
    int di = blockIdx.x;           // 0..730
    float delta = (float)(di - 365);
    int d = threadIdx.x;           // 0..127
    float v = wt1[d] * delta + bt1[d] + sinf(wt2[d] * delta + bt2[d]);
    hh[d] = v;
    Hmsg[(size_t)di * 128 + d] = v;
    __syncthreads();
    if (d < 64) {
        const float* W = Wtau_l + (size_t)d * 128;
        float s = 0.f;
#pragma unroll
        for (int k = 0; k < 128; k += 4) {
            float4 w = *(const float4*)(W + k);
            s += hh[k] * w.x + hh[k + 1] * w.y + hh[k + 2] * w.z + hh[k + 3] * w.w;
        }
        Hattn[(size_t)di * 64 + d] = s;
    }
}

// ---------------- edge kernel: one warp per edge ----------------
__global__ void __launch_bounds__(256) k_edge(
    const int* __restrict__ e_sub, const int* __restrict__ e_rel,
    const int* __restrict__ e_obj, const int* __restrict__ e_ridx,
    const int* __restrict__ e_tau, const int* __restrict__ q_tau,
    const float* __restrict__ HS, const float* __restrict__ Rattn,
    const float* __restrict__ Qattn, const float* __restrict__ Hattn,
    const float* __restrict__ Hmsg, const float* __restrict__ hprev,
    const float* __restrict__ rela_l, const float* __restrict__ walpha_w_l,
    const float* __restrict__ walpha_b_l, float* __restrict__ agg)
{
    int e = (int)((blockIdx.x * blockDim.x + threadIdx.x) >> 5);
    int lane = threadIdx.x & 31;
    if (e >= N_EDGE) return;

    int s_ = e_sub[e];
    int r_ = e_rel[e];
    int o_ = e_obj[e];
    int q_ = e_ridx[e];
    int t_ = e_tau[e];
    int tq = q_tau[q_];
    int tau = (t_ >= 0) ? t_ : tq;
    int di = tau - tq + 365;
    di = min(max(di, 0), 730);

    float2 hs2 = ((const float2*)HS)   [(size_t)s_ * 32 + lane];
    float2 rr2 = ((const float2*)Rattn)[(size_t)r_ * 32 + lane];
    float2 qq2 = ((const float2*)Qattn)[(size_t)q_ * 32 + lane];
    float2 tt2 = ((const float2*)Hattn)[(size_t)di * 32 + lane];
    float vx = fmaxf(hs2.x + rr2.x + qq2.x + tt2.x, 0.f);
    float vy = fmaxf(hs2.y + rr2.y + qq2.y + tt2.y, 0.f);
    float2 wa = ((const float2*)walpha_w_l)[lane];
    float acc = vx * wa.x + vy * wa.y;
#pragma unroll
    for (int off = 16; off; off >>= 1) acc += __shfl_xor_sync(0xffffffffu, acc, off);
    float alpha = 1.0f / (1.0f + expf(-(acc + walpha_b_l[0])));

    float4 h4 = ((const float4*)hprev) [(size_t)s_ * 32 + lane];
    float4 r4 = ((const float4*)rela_l)[(size_t)r_ * 32 + lane];
    float4 m4 = ((const float4*)Hmsg)  [(size_t)di * 32 + lane];
    float mx = alpha * (h4.x + r4.x + m4.x);
    float my = alpha * (h4.y + r4.y + m4.y);
    float mz = alpha * (h4.z + r4.z + m4.z);
    float mw = alpha * (h4.w + r4.w + m4.w);
    float* dst = agg + (size_t)o_ * 128 + lane * 4;
    asm volatile("red.global.add.v4.f32 [%0], {%1,%2,%3,%4};"
                 :: "l"(dst), "f"(mx), "f"(my), "f"(mz), "f"(mw) : "memory");
}

// ---------------- tensor-core GEMM v3: bf16 split planes in smem ----------------
// C[M,NOUT] = A[M,128] @ W[NOUT,128]^T (+bias)(+relu), NOUT multiple of 64.
// 256 thr = 8 warps (4m x 2n), BM=128, n-tiles of 64 looped internally.
// Planes: Ah/Al [128][AST], Bh/Bl [64][AST] of bf16x2-packed k-pairs.
// 3-term compensation: hi*hi + hi*lo + lo*hi (bf16 m16n8k16).
// blockIdx.y==1 selects the second independent problem (gi/gh batching).
__global__ void __launch_bounds__(256, 2) k_mma(
    const float* __restrict__ A, const float* __restrict__ W,
    const float* __restrict__ bias, float* __restrict__ C,
    const float* __restrict__ A2, const float* __restrict__ W2,
    const float* __restrict__ bias2, float* __restrict__ C2,
    int M, int NOUT, int relu)
{
    if (blockIdx.y == 1) { A = A2; W = W2; bias = bias2; C = C2; }
    extern __shared__ unsigned sm[];
    unsigned* Ah = sm;                  // [128][AST]
    unsigned* Al = sm + 128 * AST;
    unsigned* Bh = sm + 256 * AST;      // [64][AST]
    unsigned* Bl = sm + 320 * AST;

    int tid  = threadIdx.x;
    int bm   = blockIdx.x * 128;
    int lane = tid & 31;
    int warp = tid >> 5;
    int wm   = (warp & 3) * 32;   // 0,32,64,96
    int wn   = (warp >> 2) * 32;  // 0,32
    int gr   = lane >> 2;         // 0..7
    int tg   = lane & 3;          // 0..3

    // ---- load + split A tile (128 x 128) ----
    for (int i = tid; i < 128 * 32; i += 256) {
        int row = i >> 5;
        int c4  = (i & 31) * 4;       // element col, pairs c4/2, c4/2+1
        int grow = bm + row;
        float4 v = (grow < M) ? *(const float4*)(A + (size_t)grow * 128 + c4)
                              : make_float4(0.f, 0.f, 0.f, 0.f);
        unsigned h0, l0, h1, l1;
        split_pair(v.x, v.y, h0, l0);
        split_pair(v.z, v.w, h1, l1);
        int p = row * AST + (c4 >> 1);
        Ah[p] = h0; Ah[p + 1] = h1;
        Al[p] = l0; Al[p + 1] = l1;
    }
    __syncthreads();

    for (int nb = 0; nb < NOUT; nb += 64) {
        // ---- load + split B tile (64 x 128) ----
        for (int i = tid; i < 64 * 32; i += 256) {
            int row = i >> 5;
            int c4  = (i & 31) * 4;
            float4 v = *(const float4*)(W + (size_t)(nb + row) * 128 + c4);
            unsigned h0, l0, h1, l1;
            split_pair(v.x, v.y, h0, l0);
            split_pair(v.z, v.w, h1, l1);
            int p = row * AST + (c4 >> 1);
            Bh[p] = h0; Bh[p + 1] = h1;
            Bl[p] = l0; Bl[p + 1] = l1;
        }
        __syncthreads();

        float acc[2][4][4];
#pragma unroll
        for (int mt = 0; mt < 2; mt++)
#pragma unroll
            for (int nt = 0; nt < 4; nt++)
#pragma unroll
                for (int r = 0; r < 4; r++) acc[mt][nt][r] = 0.f;

#pragma unroll
        for (int it = 0; it < 8; it++) {      // k16 chunks over K=128
            int p0 = it * 8 + tg;             // k-pair index
            unsigned ah[2][4], al[2][4];
#pragma unroll
            for (int mt = 0; mt < 2; mt++) {
                int base = (wm + mt * 16 + gr) * AST + p0;
                ah[mt][0] = Ah[base];
                ah[mt][1] = Ah[base + 8 * AST];
                ah[mt][2] = Ah[base + 4];
                ah[mt][3] = Ah[base + 8 * AST + 4];
                al[mt][0] = Al[base];
                al[mt][1] = Al[base + 8 * AST];
                al[mt][2] = Al[base + 4];
                al[mt][3] = Al[base + 8 * AST + 4];
            }
            unsigned bh[4][2], bl[4][2];
#pragma unroll
            for (int nt = 0; nt < 4; nt++) {
                int base = (wn + nt * 8 + gr) * AST + p0;
                bh[nt][0] = Bh[base];
                bh[nt][1] = Bh[base + 4];
                bl[nt][0] = Bl[base];
                bl[nt][1] = Bl[base + 4];
            }
#pragma unroll
            for (int mt = 0; mt < 2; mt++)
#pragma unroll
                for (int nt = 0; nt < 4; nt++) {
                    mma_bf16(acc[mt][nt], ah[mt][0], ah[mt][1], ah[mt][2], ah[mt][3],
                             bh[nt][0], bh[nt][1]);
                    mma_bf16(acc[mt][nt], ah[mt][0], ah[mt][1], ah[mt][2], ah[mt][3],
                             bl[nt][0], bl[nt][1]);
                    mma_bf16(acc[mt][nt], al[mt][0], al[mt][1], al[mt][2], al[mt][3],
                             bh[nt][0], bh[nt][1]);
                }
        }
        __syncthreads();  // done reading B planes before next tile overwrite

        // ---- epilogue for this n-tile ----
#pragma unroll
        for (int mt = 0; mt < 2; mt++) {
#pragma unroll
            for (int nt = 0; nt < 4; nt++) {
                int col = nb + wn + nt * 8 + 2 * tg;
                float bx = 0.f, by = 0.f;
                if (bias) { bx = bias[col]; by = bias[col + 1]; }
                int row0 = bm + wm + mt * 16 + gr;
                int row1 = row0 + 8;
                float2 v0 = make_float2(acc[mt][nt][0] + bx, acc[mt][nt][1] + by);
                float2 v1 = make_float2(acc[mt][nt][2] + bx, acc[mt][nt][3] + by);
                if (relu) {
                    v0.x = fmaxf(v0.x, 0.f); v0.y = fmaxf(v0.y, 0.f);
                    v1.x = fmaxf(v1.x, 0.f); v1.y = fmaxf(v1.y, 0.f);
                }
                if (row0 < M) *(float2*)(C + (size_t)row0 * NOUT + col) = v0;
                if (row1 < M) *(float2*)(C + (size_t)row1 * NOUT + col) = v1;
            }
        }
    }
}

// ---------------- GRU elementwise; gh==nullptr means hprev was 0 -> gh gates = bhh ----------------
__global__ void k_gru(const float* __restrict__ gi, const float* __restrict__ gh,
                      const float* __restrict__ bhh, float* __restrict__ h)
{
    int idx = blockIdx.x * blockDim.x + threadIdx.x;  // node*32 + g
    if (idx >= N_NODE * 32) return;
    int n = idx >> 5, g = idx & 31;
    const float4* gi4 = (const float4*)(gi + (size_t)n * 384);
    float4 ir = gi4[g], iz = gi4[32 + g], in_ = gi4[64 + g];
    float4 hr, hz, hn;
    if (gh) {
        const float4* gh4 = (const float4*)(gh + (size_t)n * 384);
        hr = gh4[g]; hz = gh4[32 + g]; hn = gh4[64 + g];
    } else {
        const float4* b4 = (const float4*)bhh;
        hr = b4[g]; hz = b4[32 + g]; hn = b4[64 + g];
    }
    float4 h0 = ((const float4*)h)[(size_t)n * 32 + g];
    float4 out;
    {
        float r = sigmoidf_(ir.x + hr.x), z = sigmoidf_(iz.x + hz.x);
        float nn = tanhf(in_.x + r * hn.x);
        out.x = (1.f - z) * nn + z * h0.x;
    }
    {
        float r = sigmoidf_(ir.y + hr.y), z = sigmoidf_(iz.y + hz.y);
        float nn = tanhf(in_.y + r * hn.y);
        out.y = (1.f - z) * nn + z * h0.y;
    }
    {
        float r = sigmoidf_(ir.z + hr.z), z = sigmoidf_(iz.z + hz.z);
        float nn = tanhf(in_.z + r * hn.z);
        out.z = (1.f - z) * nn + z * h0.z;
    }
    {
        float r = sigmoidf_(ir.w + hr.w), z = sigmoidf_(iz.w + hz.w);
        float nn = tanhf(in_.w + r * hn.w);
        out.w = (1.f - z) * nn + z * h0.w;
    }
    ((float4*)h)[(size_t)n * 32 + g] = out;
}

// ---------------- output scatter: deterministic last-index-wins on collisions ----------------
__global__ void k_scat1(const int* __restrict__ nb, const int* __restrict__ ne,
                        int* __restrict__ winner, int n_ent)
{
    int n = blockIdx.x * blockDim.x + threadIdx.x;
    if (n >= N_NODE) return;
    size_t slot = (size_t)nb[n] * n_ent + ne[n];
    atomicMax(&winner[slot], n);
}

__global__ void k_scat2(const float* __restrict__ h, const float* __restrict__ Wfinal,
                        const int* __restrict__ nb, const int* __restrict__ ne,
                        const int* __restrict__ winner, float* __restrict__ out, int n_ent)
{
    int n = (int)((blockIdx.x * blockDim.x + threadIdx.x) >> 5);
    int lane = threadIdx.x & 31;
    if (n >= N_NODE) return;
    float4 hv = ((const float4*)h)[(size_t)n * 32 + lane];
    float4 wv = ((const float4*)Wfinal)[lane];
    float s = hv.x * wv.x + hv.y * wv.y + hv.z * wv.z + hv.w * wv.w;
#pragma unroll
    for (int off = 16; off; off >>= 1) s += __shfl_xor_sync(0xffffffffu, s, off);
    if (lane == 0) {
        size_t slot = (size_t)nb[n] * n_ent + ne[n];
        if (winner[slot] == n) out[slot] = s;
    }
}

// ---------------- host launcher ----------------
extern "C" void kernel_launch(void* const* d_in, const int* in_sizes, int n_in,
                              void* d_out, int out_size)
{
    const float* rela     = (const float*)d_in[0];
    const float* Ws       = (const float*)d_in[1];
    const float* Wr       = (const float*)d_in[2];
    const float* Wqr_w    = (const float*)d_in[3];
    const float* Wqr_b    = (const float*)d_in[4];
    const float* Wtau     = (const float*)d_in[5];
    const float* walpha_w = (const float*)d_in[6];
    const float* walpha_b = (const float*)d_in[7];
    const float* Wh       = (const float*)d_in[8];
    const float* wt1      = (const float*)d_in[9];
    const float* bt1      = (const float*)d_in[10];
    const float* wt2      = (const float*)d_in[11];
    const float* bt2      = (const float*)d_in[12];
    const float* Wih      = (const float*)d_in[13];
    const float* Whh      = (const float*)d_in[14];
    const float* bih      = (const float*)d_in[15];
    const float* bhh      = (const float*)d_in[16];
    const float* Wfinal   = (const float*)d_in[17];
    const int*   q_rel    = (const int*)d_in[18];
    const int*   q_tau    = (const int*)d_in[19];
    const int*   e_ridx   = (const int*)d_in[20];
    const int*   e_rel    = (const int*)d_in[21];
    const int*   e_tau    = (const int*)d_in[22];
    const int*   e_sub    = (const int*)d_in[23];
    const int*   e_obj    = (const int*)d_in[24];
    const int*   nb       = (const int*)d_in[25];
    const int*   ne       = (const int*)d_in[26];

    int nq    = in_sizes[18];
    int n_ent = out_size / nq;

    float *hprev, *hidden1, *agg, *gi, *gh, *HS, *Rattn, *Qattn, *Hattn, *Hmsg;
    int* winner;
    cudaGetSymbolAddress((void**)&hprev,   g_hprev);
    cudaGetSymbolAddress((void**)&hidden1, g_hidden1);
    cudaGetSymbolAddress((void**)&agg,     g_agg);
    cudaGetSymbolAddress((void**)&gi,      g_gi);
    cudaGetSymbolAddress((void**)&gh,      g_gh);
    cudaGetSymbolAddress((void**)&HS,      g_HS);
    cudaGetSymbolAddress((void**)&Rattn,   g_Rattn);
    cudaGetSymbolAddress((void**)&Qattn,   g_Qattn);
    cudaGetSymbolAddress((void**)&Hattn,   g_Hattn);
    cudaGetSymbolAddress((void**)&Hmsg,    g_Hmsg);
    cudaGetSymbolAddress((void**)&winner,  g_winner);

    cudaFuncSetAttribute(k_mma, cudaFuncAttributeMaxDynamicSharedMemorySize, SMEM_MMA);

    cudaMemsetAsync(hprev, 0, sizeof(float) * (size_t)N_NODE * D_DIM);
    cudaMemsetAsync(HS,    0, sizeof(float) * (size_t)N_NODE * A_DIM);  // layer-0: hprev@Ws^T == 0

    const int mblocks = (N_NODE + 127) / 128;   // 782
    dim3 g1(mblocks, 1), g2(mblocks, 2);

    for (int l = 0; l < L_LAYERS; l++) {
        cudaMemsetAsync(agg, 0, sizeof(float) * (size_t)N_NODE * D_DIM);

        k_tab_rq<<<NREL + NQ_C, 64>>>(rela + (size_t)l * NREL * 128,
                                      Wr + (size_t)l * 64 * 128,
                                      Wqr_w + (size_t)l * 64 * 128,
                                      Wqr_b + (size_t)l * 64,
                                      q_rel, Rattn, Qattn);
        k_tab_delta<<<N_DELTA, 128>>>(wt1 + (size_t)l * 128, bt1 + (size_t)l * 128,
                                      wt2 + (size_t)l * 128, bt2 + (size_t)l * 128,
                                      Wtau + (size_t)l * 64 * 128, Hmsg, Hattn);
        if (l > 0) {
            // HS = hprev @ Ws^T  [N_NODE, 64]   (layer 0: hprev==0 -> HS memset above)
            k_mma<<<g1, 256, SMEM_MMA>>>(hprev, Ws + (size_t)l * 64 * 128, nullptr, HS,
                                         nullptr, nullptr, nullptr, nullptr,
                                         N_NODE, 64, 0);
        }

        k_edge<<<N_EDGE / 8, 256>>>(e_sub + (size_t)l * N_EDGE, e_rel + (size_t)l * N_EDGE,
                                    e_obj + (size_t)l * N_EDGE, e_ridx + (size_t)l * N_EDGE,
                                    e_tau + (size_t)l * N_EDGE, q_tau,
                                    HS, Rattn, Qattn, Hattn, Hmsg, hprev,
                                    rela + (size_t)l * NREL * 128,
                                    walpha_w + (size_t)l * 64, walpha_b + l, agg);

        // hidden1 = relu(agg @ Wh^T)
        k_mma<<<g1, 256, SMEM_MMA>>>(agg, Wh + (size_t)l * 128 * 128, nullptr, hidden1,
                                     nullptr, nullptr, nullptr, nullptr,
                                     N_NODE, 128, 1);
        if (l > 0) {
            // batched: y=0 -> gi = hidden1@Wih^T+bih ; y=1 -> gh = hprev@Whh^T+bhh
            k_mma<<<g2, 256, SMEM_MMA>>>(hidden1, Wih + (size_t)l * 384 * 128,
                                         bih + (size_t)l * 384, gi,
                                         hprev, Whh + (size_t)l * 384 * 128,
                                         bhh + (size_t)l * 384, gh,
                                         N_NODE, 384, 0);
        } else {
            k_mma<<<g1, 256, SMEM_MMA>>>(hidden1, Wih + (size_t)l * 384 * 128,
                                         bih + (size_t)l * 384, gi,
                                         nullptr, nullptr, nullptr, nullptr,
                                         N_NODE, 384, 0);
        }
        // hprev <- GRU   (layer 0: gh gates are just bhh since hprev==0)
        k_gru<<<(N_NODE * 32) / 256, 256>>>(gi, (l > 0) ? gh : nullptr,
                                            bhh + (size_t)l * 384, hprev);
    }

    cudaMemsetAsync(d_out, 0, (size_t)out_size * sizeof(float));
    cudaMemsetAsync(winner, 0xFF, (size_t)out_size * sizeof(int));
    k_scat1<<<(N_NODE + 255) / 256, 256>>>(nb, ne, winner, n_ent);
    k_scat2<<<(N_NODE * 32) / 256, 256>>>(hprev, Wfinal, nb, ne, winner, (float*)d_out, n_ent);
}

// round 8
// speedup vs baseline: 3.8096x; 1.0169x over previous
#include <cuda_runtime.h>
#include <cuda_bf16.h>
#include <math.h>

#define L_LAYERS 3
#define D_DIM    128
#define A_DIM    64
#define NREL     401
#define N_NODE   100000
#define N_EDGE   600000
#define NQ_C     512
#define N_DELTA  731
#define MAX_OUT  (512*50000)

// k_mma smem: 4 bf16x2-packed planes, stride 68 words (64 k-pairs + pad, mod32=4)
#define AST 68
#define SMEM_MMA ((128 + 128 + 64 + 64) * AST * 4)   // 104448 B -> 2 CTAs/SM

// ---------------- static device scratch (no allocations allowed) ----------------
__device__ float g_hprev  [N_NODE * D_DIM];
__device__ float g_hidden1[N_NODE * D_DIM];
__device__ float g_agg    [N_NODE * D_DIM];
__device__ float g_gi     [N_NODE * 3 * D_DIM];
__device__ float g_gh     [N_NODE * 3 * D_DIM];
__device__ float g_HS     [N_NODE * A_DIM];
__device__ float g_Rattn  [NREL * A_DIM];
__device__ float g_Qattn  [NQ_C * A_DIM];
__device__ float g_Hattn  [N_DELTA * A_DIM];
__device__ float g_Hmsg   [N_DELTA * D_DIM];
__device__ int   g_winner [MAX_OUT];

__device__ __forceinline__ float sigmoidf_(float x) { return 1.0f / (1.0f + expf(-x)); }

// pack two fp32 into one bf16x2 word: low half = x0 (k even), high half = x1 (k+1)
__device__ __forceinline__ unsigned pack_bf2(float x0, float x1) {
    unsigned r;
    asm("cvt.rn.bf16x2.f32 %0, %1, %2;" : "=r"(r) : "f"(x1), "f"(x0));
    return r;
}
// split a pair of fp32 into (hi bf16x2 word, lo bf16x2 word)
__device__ __forceinline__ void split_pair(float x0, float x1, unsigned& h, unsigned& l) {
    h = pack_bf2(x0, x1);
    float h0 = __uint_as_float(h << 16);
    float h1 = __uint_as_float(h & 0xFFFF0000u);
    l = pack_bf2(x0 - h0, x1 - h1);
}

__device__ __forceinline__ void mma_bf16(float* c,
                                         unsigned a0, unsigned a1, unsigned a2, unsigned a3,
                                         unsigned b0, unsigned b1) {
    asm volatile(
        "mma.sync.aligned.m16n8k16.row.col.f32.bf16.bf16.f32 "
        "{%0,%1,%2,%3}, {%4,%5,%6,%7}, {%8,%9}, {%0,%1,%2,%3};"
        : "+f"(c[0]), "+f"(c[1]), "+f"(c[2]), "+f"(c[3])
        : "r"(a0), "r"(a1), "r"(a2), "r"(a3), "r"(b0), "r"(b1));
}

__device__ __forceinline__ void ldsm_x4(unsigned& r0, unsigned& r1,
                                        unsigned& r2, unsigned& r3, unsigned addr) {
    asm volatile("ldmatrix.sync.aligned.m8n8.x4.shared.b16 {%0,%1,%2,%3}, [%4];"
                 : "=r"(r0), "=r"(r1), "=r"(r2), "=r"(r3) : "r"(addr));
}

// ---------------- per-relation / per-query attention tables ----------------
__global__ void k_tab_rq(const float* __restrict__ rela_l,
                         const float* __restrict__ Wr_l,
                         const float* __restrict__ Wqr_w_l,
                         const float* __restrict__ Wqr_b_l,
                         const int*   __restrict__ q_rel,
                         float* __restrict__ Rattn,
                         float* __restrict__ Qattn)
{
    __shared__ float hv[128];
    int b = blockIdx.x;
    int a = threadIdx.x; // 0..63
    const float* src = (b < NREL) ? (rela_l + (size_t)b * 128)
                                  : (rela_l + (size_t)q_rel[b - NREL] * 128);
    hv[a] = src[a];
    hv[a + 64] = src[a + 64];
    __syncthreads();
    const float* W = ((b < NREL) ? Wr_l : Wqr_w_l) + (size_t)a * 128;
    float s = 0.f;
#pragma unroll
    for (int k = 0; k < 128; k += 4) {
        float4 w = *(const float4*)(W + k);
        s += hv[k] * w.x + hv[k + 1] * w.y + hv[k + 2] * w.z + hv[k + 3] * w.w;
    }
    if (b < NREL) Rattn[b * 64 + a] = s;
    else          Qattn[(b - NREL) * 64 + a] = s + Wqr_b_l[a];
}

// ---------------- per-delta tables: h_hau vector + h_hau @ Wtau^T ----------------
__global__ void k_tab_delta(const float* __restrict__ wt1, const float* __restrict__ bt1,
                            const float* __restrict__ wt2, const float* __restrict__ bt2,
                            const float* __restrict__ Wtau_l,
                            float* __restrict__ Hmsg, float* __restrict__ Hattn)
{
    __shared__ float hh[128];
    int di = blockIdx.x;           // 0..730
    float delta = (float)(di - 365);
    int d = threadIdx.x;           // 0..127
    float v = wt1[d] * delta + bt1[d] + sinf(wt2[d] * delta + bt2[d]);
    hh[d] = v;
    Hmsg[(size_t)di * 128 + d] = v;
    __syncthreads();
    if (d < 64) {
        const float* W = Wtau_l + (size_t)d * 128;
        float s = 0.f;
#pragma unroll
        for (int k = 0; k < 128; k += 4) {
            float4 w = *(const float4*)(W + k);
            s += hh[k] * w.x + hh[k + 1] * w.y + hh[k + 2] * w.z + hh[k + 3] * w.w;
        }
        Hattn[(size_t)di * 64 + d] = s;
    }
}

// ---------------- edge kernel: one warp per edge ----------------
// zero_h=1 (layer 0): hprev==0 -> skip HS and hprev gathers entirely.
__global__ void __launch_bounds__(256) k_edge(
    const int* __restrict__ e_sub, const int* __restrict__ e_rel,
    const int* __restrict__ e_obj, const int* __restrict__ e_ridx,
    const int* __restrict__ e_tau, const int* __restrict__ q_tau,
    const float* __restrict__ HS, const float* __restrict__ Rattn,
    const float* __restrict__ Qattn, const float* __restrict__ Hattn,
    const float* __restrict__ Hmsg, const float* __restrict__ hprev,
    const float* __restrict__ rela_l, const float* __restrict__ walpha_w_l,
    const float* __restrict__ walpha_b_l, float* __restrict__ agg, int zero_h)
{
    int e = (int)((blockIdx.x * blockDim.x + threadIdx.x) >> 5);
    int lane = threadIdx.x & 31;
    if (e >= N_EDGE) return;

    int s_ = e_sub[e];
    int r_ = e_rel[e];
    int o_ = e_obj[e];
    int q_ = e_ridx[e];
    int t_ = e_tau[e];
    int tq = q_tau[q_];
    int tau = (t_ >= 0) ? t_ : tq;
    int di = tau - tq + 365;
    di = min(max(di, 0), 730);

    float2 rr2 = ((const float2*)Rattn)[(size_t)r_ * 32 + lane];
    float2 qq2 = ((const float2*)Qattn)[(size_t)q_ * 32 + lane];
    float2 tt2 = ((const float2*)Hattn)[(size_t)di * 32 + lane];
    float ax = rr2.x + qq2.x + tt2.x;
    float ay = rr2.y + qq2.y + tt2.y;
    if (!zero_h) {
        float2 hs2 = ((const float2*)HS)[(size_t)s_ * 32 + lane];
        ax += hs2.x; ay += hs2.y;
    }
    float vx = fmaxf(ax, 0.f);
    float vy = fmaxf(ay, 0.f);
    float2 wa = ((const float2*)walpha_w_l)[lane];
    float acc = vx * wa.x + vy * wa.y;
#pragma unroll
    for (int off = 16; off; off >>= 1) acc += __shfl_xor_sync(0xffffffffu, acc, off);
    float alpha = 1.0f / (1.0f + expf(-(acc + walpha_b_l[0])));

    float4 r4 = ((const float4*)rela_l)[(size_t)r_ * 32 + lane];
    float4 m4 = ((const float4*)Hmsg)  [(size_t)di * 32 + lane];
    float mx = r4.x + m4.x, my = r4.y + m4.y, mz = r4.z + m4.z, mw = r4.w + m4.w;
    if (!zero_h) {
        float4 h4 = ((const float4*)hprev)[(size_t)s_ * 32 + lane];
        mx += h4.x; my += h4.y; mz += h4.z; mw += h4.w;
    }
    mx *= alpha; my *= alpha; mz *= alpha; mw *= alpha;
    float* dst = agg + (size_t)o_ * 128 + lane * 4;
    asm volatile("red.global.add.v4.f32 [%0], {%1,%2,%3,%4};"
                 :: "l"(dst), "f"(mx), "f"(my), "f"(mz), "f"(mw) : "memory");
}

// ---------------- tensor-core GEMM v4: bf16 split planes + ldmatrix ----------------
// Two weight segments share one A tile:
//   seg1: C1[M,N1] = A @ W1^T (+bias1)(relu1)   seg2: C2[M,N2] = A @ W2^T (+bias2)(relu2)
// 256 thr = 8 warps (4m x 2n), BM=128, 64-wide n-tiles.
__global__ void __launch_bounds__(256, 2) k_mma(
    const float* __restrict__ A, int M,
    const float* __restrict__ W1, const float* __restrict__ bias1,
    float* __restrict__ C1, int N1, int relu1,
    const float* __restrict__ W2, const float* __restrict__ bias2,
    float* __restrict__ C2, int N2, int relu2)
{
    extern __shared__ unsigned sm[];
    unsigned* Ah = sm;                  // [128][AST]
    unsigned* Al = sm + 128 * AST;
    unsigned* Bh = sm + 256 * AST;      // [64][AST]
    unsigned* Bl = sm + 320 * AST;

    int tid  = threadIdx.x;
    int bm   = blockIdx.x * 128;
    int lane = tid & 31;
    int warp = tid >> 5;
    int wm   = (warp & 3) * 32;   // 0,32,64,96
    int wn   = (warp >> 2) * 32;  // 0,32
    int gr   = lane >> 2;         // 0..7
    int tg   = lane & 3;          // 0..3
    int quad = lane >> 3;         // 0..3
    int lrow = lane & 7;          // 0..7

    // ---- load + split A tile (128 x 128) ----
    for (int i = tid; i < 128 * 32; i += 256) {
        int row = i >> 5;
        int c4  = (i & 31) * 4;
        int grow = bm + row;
        float4 v = (grow < M) ? *(const float4*)(A + (size_t)grow * 128 + c4)
                              : make_float4(0.f, 0.f, 0.f, 0.f);
        unsigned h0, l0, h1, l1;
        split_pair(v.x, v.y, h0, l0);
        split_pair(v.z, v.w, h1, l1);
        int p = row * AST + (c4 >> 1);
        Ah[p] = h0; Ah[p + 1] = h1;
        Al[p] = l0; Al[p + 1] = l1;
    }
    __syncthreads();

    // ---- per-thread ldmatrix base addresses (bytes) ----
    unsigned AhU = (unsigned)__cvta_generic_to_shared(Ah);
    unsigned AlU = (unsigned)__cvta_generic_to_shared(Al);
    unsigned BhU = (unsigned)__cvta_generic_to_shared(Bh);
    unsigned BlU = (unsigned)__cvta_generic_to_shared(Bl);
    // A: matrices [m0-7 klo][m8-15 klo][m0-7 khi][m8-15 khi]
    unsigned aOff = (unsigned)(((wm + (quad & 1) * 8 + lrow) * AST) * 4 + (quad >> 1) * 16);
    unsigned aAd[2][2];
    aAd[0][0] = AhU + aOff;            aAd[0][1] = AlU + aOff;
    aAd[1][0] = AhU + aOff + 16 * AST * 4;  aAd[1][1] = AlU + aOff + 16 * AST * 4;
    // B: rows wn+lane, matrices = 4 consecutive 8-row groups (nt 0..3)
    unsigned bOff = (unsigned)(((wn + lane) * AST) * 4);
    unsigned bAdH = BhU + bOff;
    unsigned bAdL = BlU + bOff;

    int Ntot = N1 + N2;
    for (int nb = 0; nb < Ntot; nb += 64) {
        const float* Wseg; const float* bseg; float* Cseg; int nloc, Nseg, reluseg;
        if (nb < N1) { Wseg = W1; bseg = bias1; Cseg = C1; nloc = nb;      Nseg = N1; reluseg = relu1; }
        else         { Wseg = W2; bseg = bias2; Cseg = C2; nloc = nb - N1; Nseg = N2; reluseg = relu2; }

        // ---- load + split B tile (64 x 128) ----
        for (int i = tid; i < 64 * 32; i += 256) {
            int row = i >> 5;
            int c4  = (i & 31) * 4;
            float4 v = *(const float4*)(Wseg + (size_t)(nloc + row) * 128 + c4);
            unsigned h0, l0, h1, l1;
            split_pair(v.x, v.y, h0, l0);
            split_pair(v.z, v.w, h1, l1);
            int p = row * AST + (c4 >> 1);
            Bh[p] = h0; Bh[p + 1] = h1;
            Bl[p] = l0; Bl[p + 1] = l1;
        }
        __syncthreads();

        float acc[2][4][4];
#pragma unroll
        for (int mt = 0; mt < 2; mt++)
#pragma unroll
            for (int nt = 0; nt < 4; nt++)
#pragma unroll
                for (int r = 0; r < 4; r++) acc[mt][nt][r] = 0.f;

#pragma unroll
        for (int it = 0; it < 8; it++) {      // k16 chunks over K=128
            unsigned off = it * 32;           // 8 words = 32 bytes
            unsigned ah[2][4], al[2][4];
#pragma unroll
            for (int mt = 0; mt < 2; mt++) {
                ldsm_x4(ah[mt][0], ah[mt][1], ah[mt][2], ah[mt][3], aAd[mt][0] + off);
                ldsm_x4(al[mt][0], al[mt][1], al[mt][2], al[mt][3], aAd[mt][1] + off);
            }
            unsigned bhlo[4], bhhi[4], bllo[4], blhi[4];
            ldsm_x4(bhlo[0], bhlo[1], bhlo[2], bhlo[3], bAdH + off);
            ldsm_x4(bhhi[0], bhhi[1], bhhi[2], bhhi[3], bAdH + off + 16);
            ldsm_x4(bllo[0], bllo[1], bllo[2], bllo[3], bAdL + off);
            ldsm_x4(blhi[0], blhi[1], blhi[2], blhi[3], bAdL + off + 16);
#pragma unroll
            for (int mt = 0; mt < 2; mt++)
#pragma unroll
                for (int nt = 0; nt < 4; nt++) {
                    mma_bf16(acc[mt][nt], ah[mt][0], ah[mt][1], ah[mt][2], ah[mt][3],
                             bhlo[nt], bhhi[nt]);
                    mma_bf16(acc[mt][nt], ah[mt][0], ah[mt][1], ah[mt][2], ah[mt][3],
                             bllo[nt], blhi[nt]);
                    mma_bf16(acc[mt][nt], al[mt][0], al[mt][1], al[mt][2], al[mt][3],
                             bhlo[nt], bhhi[nt]);
                }
        }
        __syncthreads();  // done reading B planes before next tile overwrite

        // ---- epilogue for this n-tile ----
#pragma unroll
        for (int mt = 0; mt < 2; mt++) {
#pragma unroll
            for (int nt = 0; nt < 4; nt++) {
                int col = nloc + wn + nt * 8 + 2 * tg;
                float bx = 0.f, by = 0.f;
                if (bseg) { bx = bseg[col]; by = bseg[col + 1]; }
                int row0 = bm + wm + mt * 16 + gr;
                int row1 = row0 + 8;
                float2 v0 = make_float2(acc[mt][nt][0] + bx, acc[mt][nt][1] + by);
                float2 v1 = make_float2(acc[mt][nt][2] + bx, acc[mt][nt][3] + by);
                if (reluseg) {
                    v0.x = fmaxf(v0.x, 0.f); v0.y = fmaxf(v0.y, 0.f);
                    v1.x = fmaxf(v1.x, 0.f); v1.y = fmaxf(v1.y, 0.f);
                }
                if (row0 < M) *(float2*)(Cseg + (size_t)row0 * Nseg + col) = v0;
                if (row1 < M) *(float2*)(Cseg + (size_t)row1 * Nseg + col) = v1;
            }
        }
    }
}

// ---------------- GRU elementwise; gh==nullptr means hprev was 0 -> gh gates = bhh ----------------
__global__ void k_gru(const float* __restrict__ gi, const float* __restrict__ gh,
                      const float* __restrict__ bhh, float* __restrict__ h)
{
    int idx = blockIdx.x * blockDim.x + threadIdx.x;  // node*32 + g
    if (idx >= N_NODE * 32) return;
    int n = idx >> 5, g = idx & 31;
    const float4* gi4 = (const float4*)(gi + (size_t)n * 384);
    float4 ir = gi4[g], iz = gi4[32 + g], in_ = gi4[64 + g];
    float4 hr, hz, hn;
    if (gh) {
        const float4* gh4 = (const float4*)(gh + (size_t)n * 384);
        hr = gh4[g]; hz = gh4[32 + g]; hn = gh4[64 + g];
    } else {
        const float4* b4 = (const float4*)bhh;
        hr = b4[g]; hz = b4[32 + g]; hn = b4[64 + g];
    }
    float4 h0 = ((const float4*)h)[(size_t)n * 32 + g];
    float4 out;
    {
        float r = sigmoidf_(ir.x + hr.x), z = sigmoidf_(iz.x + hz.x);
        float nn = tanhf(in_.x + r * hn.x);
        out.x = (1.f - z) * nn + z * h0.x;
    }
    {
        float r = sigmoidf_(ir.y + hr.y), z = sigmoidf_(iz.y + hz.y);
        float nn = tanhf(in_.y + r * hn.y);
        out.y = (1.f - z) * nn + z * h0.y;
    }
    {
        float r = sigmoidf_(ir.z + hr.z), z = sigmoidf_(iz.z + hz.z);
        float nn = tanhf(in_.z + r * hn.z);
        out.z = (1.f - z) * nn + z * h0.z;
    }
    {
        float r = sigmoidf_(ir.w + hr.w), z = sigmoidf_(iz.w + hz.w);
        float nn = tanhf(in_.w + r * hn.w);
        out.w = (1.f - z) * nn + z * h0.w;
    }
    ((float4*)h)[(size_t)n * 32 + g] = out;
}

// ---------------- output scatter: deterministic last-index-wins on collisions ----------------
__global__ void k_scat1(const int* __restrict__ nb, const int* __restrict__ ne,
                        int* __restrict__ winner, int n_ent)
{
    int n = blockIdx.x * blockDim.x + threadIdx.x;
    if (n >= N_NODE) return;
    size_t slot = (size_t)nb[n] * n_ent + ne[n];
    atomicMax(&winner[slot], n);
}

__global__ void k_scat2(const float* __restrict__ h, const float* __restrict__ Wfinal,
                        const int* __restrict__ nb, const int* __restrict__ ne,
                        const int* __restrict__ winner, float* __restrict__ out, int n_ent)
{
    int n = (int)((blockIdx.x * blockDim.x + threadIdx.x) >> 5);
    int lane = threadIdx.x & 31;
    if (n >= N_NODE) return;
    float4 hv = ((const float4*)h)[(size_t)n * 32 + lane];
    float4 wv = ((const float4*)Wfinal)[lane];
    float s = hv.x * wv.x + hv.y * wv.y + hv.z * wv.z + hv.w * wv.w;
#pragma unroll
    for (int off = 16; off; off >>= 1) s += __shfl_xor_sync(0xffffffffu, s, off);
    if (lane == 0) {
        size_t slot = (size_t)nb[n] * n_ent + ne[n];
        if (winner[slot] == n) out[slot] = s;
    }
}

// ---------------- host launcher ----------------
extern "C" void kernel_launch(void* const* d_in, const int* in_sizes, int n_in,
                              void* d_out, int out_size)
{
    const float* rela     = (const float*)d_in[0];
    const float* Ws       = (const float*)d_in[1];
    const float* Wr       = (const float*)d_in[2];
    const float* Wqr_w    = (const float*)d_in[3];
    const float* Wqr_b    = (const float*)d_in[4];
    const float* Wtau     = (const float*)d_in[5];
    const float* walpha_w = (const float*)d_in[6];
    const float* walpha_b = (const float*)d_in[7];
    const float* Wh       = (const float*)d_in[8];
    const float* wt1      = (const float*)d_in[9];
    const float* bt1      = (const float*)d_in[10];
    const float* wt2      = (const float*)d_in[11];
    const float* bt2      = (const float*)d_in[12];
    const float* Wih      = (const float*)d_in[13];
    const float* Whh      = (const float*)d_in[14];
    const float* bih      = (const float*)d_in[15];
    const float* bhh      = (const float*)d_in[16];
    const float* Wfinal   = (const float*)d_in[17];
    const int*   q_rel    = (const int*)d_in[18];
    const int*   q_tau    = (const int*)d_in[19];
    const int*   e_ridx   = (const int*)d_in[20];
    const int*   e_rel    = (const int*)d_in[21];
    const int*   e_tau    = (const int*)d_in[22];
    const int*   e_sub    = (const int*)d_in[23];
    const int*   e_obj    = (const int*)d_in[24];
    const int*   nb       = (const int*)d_in[25];
    const int*   ne       = (const int*)d_in[26];

    int nq    = in_sizes[18];
    int n_ent = out_size / nq;

    float *hprev, *hidden1, *agg, *gi, *gh, *HS, *Rattn, *Qattn, *Hattn, *Hmsg;
    int* winner;
    cudaGetSymbolAddress((void**)&hprev,   g_hprev);
    cudaGetSymbolAddress((void**)&hidden1, g_hidden1);
    cudaGetSymbolAddress((void**)&agg,     g_agg);
    cudaGetSymbolAddress((void**)&gi,      g_gi);
    cudaGetSymbolAddress((void**)&gh,      g_gh);
    cudaGetSymbolAddress((void**)&HS,      g_HS);
    cudaGetSymbolAddress((void**)&Rattn,   g_Rattn);
    cudaGetSymbolAddress((void**)&Qattn,   g_Qattn);
    cudaGetSymbolAddress((void**)&Hattn,   g_Hattn);
    cudaGetSymbolAddress((void**)&Hmsg,    g_Hmsg);
    cudaGetSymbolAddress((void**)&winner,  g_winner);

    cudaFuncSetAttribute(k_mma, cudaFuncAttributeMaxDynamicSharedMemorySize, SMEM_MMA);

    cudaMemsetAsync(hprev, 0, sizeof(float) * (size_t)N_NODE * D_DIM);

    const int mblocks = (N_NODE + 127) / 128;   // 782

    for (int l = 0; l < L_LAYERS; l++) {
        cudaMemsetAsync(agg, 0, sizeof(float) * (size_t)N_NODE * D_DIM);

        k_tab_rq<<<NREL + NQ_C, 64>>>(rela + (size_t)l * NREL * 128,
                                      Wr + (size_t)l * 64 * 128,
                                      Wqr_w + (size_t)l * 64 * 128,
                                      Wqr_b + (size_t)l * 64,
                                      q_rel, Rattn, Qattn);
        k_tab_delta<<<N_DELTA, 128>>>(wt1 + (size_t)l * 128, bt1 + (size_t)l * 128,
                                      wt2 + (size_t)l * 128, bt2 + (size_t)l * 128,
                                      Wtau + (size_t)l * 64 * 128, Hmsg, Hattn);
        if (l > 0) {
            // shared-A launch: HS = hprev@Ws^T  and  gh = hprev@Whh^T + bhh
            k_mma<<<mblocks, 256, SMEM_MMA>>>(hprev, N_NODE,
                                              Ws + (size_t)l * 64 * 128, nullptr, HS, 64, 0,
                                              Whh + (size_t)l * 384 * 128,
                                              bhh + (size_t)l * 384, gh, 384, 0);
        }

        k_edge<<<N_EDGE / 8, 256>>>(e_sub + (size_t)l * N_EDGE, e_rel + (size_t)l * N_EDGE,
                                    e_obj + (size_t)l * N_EDGE, e_ridx + (size_t)l * N_EDGE,
                                    e_tau + (size_t)l * N_EDGE, q_tau,
                                    HS, Rattn, Qattn, Hattn, Hmsg, hprev,
                                    rela + (size_t)l * NREL * 128,
                                    walpha_w + (size_t)l * 64, walpha_b + l, agg,
                                    (l == 0) ? 1 : 0);

        // hidden1 = relu(agg @ Wh^T)
        k_mma<<<mblocks, 256, SMEM_MMA>>>(agg, N_NODE,
                                          Wh + (size_t)l * 128 * 128, nullptr, hidden1, 128, 1,
                                          nullptr, nullptr, nullptr, 0, 0);
        // gi = hidden1 @ Wih^T + bih
        k_mma<<<mblocks, 256, SMEM_MMA>>>(hidden1, N_NODE,
                                          Wih + (size_t)l * 384 * 128,
                                          bih + (size_t)l * 384, gi, 384, 0,
                                          nullptr, nullptr, nullptr, 0, 0);
        // hprev <- GRU   (layer 0: gh gates are just bhh since hprev==0)
        k_gru<<<(N_NODE * 32) / 256, 256>>>(gi, (l > 0) ? gh : nullptr,
                                            bhh + (size_t)l * 384, hprev);
    }

    cudaMemsetAsync(d_out, 0, (size_t)out_size * sizeof(float));
    cudaMemsetAsync(winner, 0xFF, (size_t)out_size * sizeof(int));
    k_scat1<<<(N_NODE + 255) / 256, 256>>>(nb, ne, winner, n_ent);
    k_scat2<<<(N_NODE * 32) / 256, 256>>>(hprev, Wfinal, nb, ne, winner, (float*)d_out, n_ent);
}